// round 14
// baseline (speedup 1.0000x reference)
#include <cuda_runtime.h>
#include <cuda_bf16.h>
#include <cstdint>

typedef __nv_bfloat16 bf16;
typedef unsigned long long u64;

// ---------------- problem constants ----------------
#define NNODES 5000
#define NEDGE  8192
#define DDIM   200
#define NLAYER 6
#define NFILT  96
#define FLATSZ 18816      // 96*14*14 = 294*64
#define NCLASS 13

#define MPADX   5120
#define KPAD    256
#define E2      (2*NEDGE)

// ---------------- device scratch (static, no allocs) ----------------
__device__ __align__(256) float g_x[NNODES * DDIM];
__device__ __align__(256) bf16  g_xhi[MPADX * KPAD], g_xlo[MPADX * KPAD];
__device__ __align__(256) bf16  g_relhi[2][E2 * KPAD], g_rello[2][E2 * KPAD];
__device__ __align__(256) bf16  g_thi[E2 * KPAD], g_tlo[E2 * KPAD];
__device__ __align__(256) float g_agg[NNODES * DDIM];
__device__ __align__(256) float g_deg[2 * NNODES];
__device__ __align__(256) float g_scale[2 * NEDGE];
__device__ __align__(256) bf16  g_hfhi[(size_t)NEDGE * FLATSZ], g_hflo[(size_t)NEDGE * FLATSZ];
__device__ __align__(256) float g_h2[NEDGE * DDIM];
__device__ __align__(256) bf16  g_wthi[24 * KPAD * KPAD], g_wtlo[24 * KPAD * KPAD];
__device__ __align__(256) bf16  g_fchi[256 * FLATSZ], g_fclo[256 * FLATSZ];

// ---------------- fp32x2 / bf16 helpers ----------------
__device__ __forceinline__ void fma2(u64& d, u64 a, u64 b) {
    asm("fma.rn.f32x2 %0, %1, %2, %0;" : "+l"(d) : "l"(a), "l"(b));
}
__device__ __forceinline__ float2 unpk(u64 v) {
    float2 r; asm("mov.b64 {%0, %1}, %2;" : "=f"(r.x), "=f"(r.y) : "l"(v)); return r;
}
__device__ __forceinline__ u64 pk2(float a, float b) {
    u64 r; asm("mov.b64 %0, {%1, %2};" : "=l"(r) : "f"(a), "f"(b)); return r;
}
__device__ __forceinline__ void split2(float v, bf16& h, bf16& l) {
    h = __float2bfloat16(v);
    l = __float2bfloat16(v - __bfloat162float(h));
}

// ---------------- mma.sync / ldmatrix / cp.async helpers ----------------
__device__ __forceinline__ uint32_t smem_u32(const void* p) {
    uint32_t a;
    asm("{ .reg .u64 t; cvta.to.shared.u64 t, %1; cvt.u32.u64 %0, t; }" : "=r"(a) : "l"(p));
    return a;
}
__device__ __forceinline__ void ldm4(uint32_t addr, uint32_t* r) {
    asm volatile("ldmatrix.sync.aligned.m8n8.x4.shared.b16 {%0,%1,%2,%3}, [%4];"
                 : "=r"(r[0]), "=r"(r[1]), "=r"(r[2]), "=r"(r[3]) : "r"(addr));
}
__device__ __forceinline__ void ldm2(uint32_t addr, uint32_t* r) {
    asm volatile("ldmatrix.sync.aligned.m8n8.x2.shared.b16 {%0,%1}, [%2];"
                 : "=r"(r[0]), "=r"(r[1]) : "r"(addr));
}
__device__ __forceinline__ void mma16816(float* c, const uint32_t* a,
                                         uint32_t b0, uint32_t b1) {
    asm volatile(
        "mma.sync.aligned.m16n8k16.row.col.f32.bf16.bf16.f32 "
        "{%0,%1,%2,%3}, {%4,%5,%6,%7}, {%8,%9}, {%0,%1,%2,%3};"
        : "+f"(c[0]), "+f"(c[1]), "+f"(c[2]), "+f"(c[3])
        : "r"(a[0]), "r"(a[1]), "r"(a[2]), "r"(a[3]), "r"(b0), "r"(b1));
}
#define CPA16(dst, src) \
    asm volatile("cp.async.cg.shared.global [%0], [%1], 16;" :: "r"(dst), "l"(src) : "memory")
#define CPA_COMMIT() asm volatile("cp.async.commit_group;" ::: "memory")

// ------- GEMM core: CTA tile 128x64, K-chunk 64, 8 warps (4m x 2n), 2 CTAs/SM -------
#define STGBYTES 55296
#define ALO_OFF  18432
#define BHI_OFF  36864
#define BLO_OFF  46080

struct GemmJob {
    const bf16 *Ahi, *Alo; int lda;
    const bf16 *Bhi, *Blo, *Bhi2, *Blo2; int mswitch;
    int ldb, kiters, mtiles;
    float* C; int ldc;
    int M, N;
    bf16 *Chi, *Clo; int ldcbf;
    const int *eidx, *ieidx;
    const float* sc;
    int epi;  // 0 plain | 2 bf16 split | 3 atomic scatter scaled | 4 atomicAdd
};

// shared staging loads (identical for full and narrow paths)
#define DEF_LOAD_CHUNK(gAhi_, gAlo_, lda_, gBhi_, gBlo_, ldb_)                             \
    auto load_chunk = [&](int kc, int s) {                                                  \
        const uint32_t sb = smb + s * STGBYTES;                                             \
        const size_t koff = (size_t)kc * 64;                                                \
        _Pragma("unroll") for (int jv = 0; jv < 4; jv++) {                                  \
            const int id = tid + jv * 256;                                                  \
            const int r = id >> 3, c = id & 7;                                              \
            const uint32_t off = (uint32_t)(r * 144 + c * 16);                              \
            const size_t src = (size_t)r * (lda_) + koff + c * 8;                           \
            CPA16(sb + off,           (gAhi_) + src);                                       \
            CPA16(sb + ALO_OFF + off, (gAlo_) + src);                                       \
        }                                                                                   \
        _Pragma("unroll") for (int jv = 0; jv < 2; jv++) {                                  \
            const int id = tid + jv * 256;                                                  \
            const int r = id >> 3, c = id & 7;                                              \
            const uint32_t off = (uint32_t)(r * 144 + c * 16);                              \
            const size_t src = (size_t)r * (ldb_) + koff + c * 8;                           \
            CPA16(sb + BHI_OFF + off, (gBhi_) + src);                                       \
            CPA16(sb + BLO_OFF + off, (gBlo_) + src);                                      \
        }                                                                                   \
        CPA_COMMIT();                                                                       \
    };

// full 128x64 tile mainloop (round-4-validated fragment mapping)
#define GEMM_CORE(kiters_)                                                                 \
    float acc[2][4][4];                                                                     \
    _Pragma("unroll") for (int mb = 0; mb < 2; mb++)                                        \
    _Pragma("unroll") for (int nb = 0; nb < 4; nb++)                                        \
    _Pragma("unroll") for (int v = 0; v < 4; v++) acc[mb][nb][v] = 0.f;                     \
    const uint32_t aRow = (uint32_t)((wm * 32 + (lane & 15)) * 144 + (lane >> 4) * 16);     \
    const int bg = lane >> 3;                                                               \
    const uint32_t bRow = (uint32_t)((wn * 32 + ((bg >> 1) * 8) + (lane & 7)) * 144         \
                                     + (bg & 1) * 16);                                      \
    load_chunk(0, 0);                                                                       \
    load_chunk(1, 1);                                                                       \
    for (int i = 0; i < (kiters_); i++) {                                                   \
        const int s = i & 1;                                                                \
        if (i + 1 < (kiters_)) asm volatile("cp.async.wait_group 1;" ::: "memory");         \
        else                   asm volatile("cp.async.wait_group 0;" ::: "memory");         \
        __syncthreads();                                                                    \
        const uint32_t sb = smb + s * STGBYTES;                                             \
        _Pragma("unroll") for (int ks = 0; ks < 4; ks++) {                                  \
            uint32_t ah[2][4], al[2][4];                                                    \
            _Pragma("unroll") for (int mb = 0; mb < 2; mb++) {                              \
                const uint32_t a = sb + aRow + (uint32_t)(mb * 16 * 144 + ks * 32);         \
                ldm4(a, ah[mb]);                                                            \
                ldm4(a + ALO_OFF, al[mb]);                                                  \
            }                                                                               \
            _Pragma("unroll") for (int p = 0; p < 2; p++) {                                 \
                uint32_t bh[4], bl[4];                                                      \
                const uint32_t b = sb + BHI_OFF + bRow + (uint32_t)(p * 16 * 144 + ks * 32);\
                ldm4(b, bh);                                                                \
                ldm4(b + (BLO_OFF - BHI_OFF), bl);                                          \
                _Pragma("unroll") for (int mb = 0; mb < 2; mb++)                            \
                _Pragma("unroll") for (int half = 0; half < 2; half++) {                    \
                    const int nb = p * 2 + half;                                            \
                    const int o = half * 2;                                                 \
                    mma16816(acc[mb][nb], ah[mb], bh[o], bh[o + 1]);                        \
                    mma16816(acc[mb][nb], al[mb], bh[o], bh[o + 1]);                        \
                    mma16816(acc[mb][nb], ah[mb], bl[o], bl[o + 1]);                        \
                }                                                                           \
            }                                                                               \
        }                                                                                   \
        __syncthreads();                                                                    \
        if (i + 2 < (kiters_)) load_chunk(i + 2, s);                                        \
    }

// narrow 128x8 tile mainloop: warp w -> rows w*16..w*16+15, cols 0..7 of the tile.
// Same staging; 1/8 the mma+ldmatrix work.
#define GEMM_CORE_N8(kiters_)                                                              \
    float accn[4] = {0.f, 0.f, 0.f, 0.f};                                                   \
    const uint32_t aRowN = (uint32_t)((wid * 16 + (lane & 15)) * 144 + (lane >> 4) * 16);   \
    const uint32_t bRowN = (uint32_t)((lane & 7) * 144 + ((lane >> 3) & 1) * 16);           \
    load_chunk(0, 0);                                                                       \
    load_chunk(1, 1);                                                                       \
    for (int i = 0; i < (kiters_); i++) {                                                   \
        const int s = i & 1;                                                                \
        if (i + 1 < (kiters_)) asm volatile("cp.async.wait_group 1;" ::: "memory");         \
        else                   asm volatile("cp.async.wait_group 0;" ::: "memory");         \
        __syncthreads();                                                                    \
        const uint32_t sb = smb + s * STGBYTES;                                             \
        _Pragma("unroll") for (int ks = 0; ks < 4; ks++) {                                  \
            uint32_t ahn[4], aln[4], bhn[2], bln[2];                                        \
            const uint32_t a = sb + aRowN + (uint32_t)(ks * 32);                            \
            ldm4(a, ahn);                                                                   \
            ldm4(a + ALO_OFF, aln);                                                         \
            const uint32_t b = sb + BHI_OFF + bRowN + (uint32_t)(ks * 32);                  \
            ldm2(b, bhn);                                                                   \
            ldm2(b + (BLO_OFF - BHI_OFF), bln);                                             \
            mma16816(accn, ahn, bhn[0], bhn[1]);                                            \
            mma16816(accn, aln, bhn[0], bhn[1]);                                            \
            mma16816(accn, ahn, bln[0], bln[1]);                                            \
        }                                                                                   \
        __syncthreads();                                                                    \
        if (i + 2 < (kiters_)) load_chunk(i + 2, s);                                        \
    }

// ---------------- merged per-layer GEMM (msg / loop / rel via blockIdx.z) ----------------
__global__ void __launch_bounds__(256, 2)
gemm_multi(GemmJob j0, GemmJob j1, GemmJob j2) {
    const GemmJob jb = (blockIdx.z == 0) ? j0 : (blockIdx.z == 1) ? j1 : j2;
    if ((int)blockIdx.y >= jb.mtiles) return;

    extern __shared__ __align__(16) char smraw[];
    const int tid  = threadIdx.x;
    const int lane = tid & 31;
    const int wid  = tid >> 5;
    const int wm   = wid >> 1;
    const int wn   = wid & 1;
    const int m0   = blockIdx.y * 128;
    const int n0   = blockIdx.x * 64;

    const bf16* Bh = (m0 >= jb.mswitch) ? jb.Bhi2 : jb.Bhi;
    const bf16* Bl = (m0 >= jb.mswitch) ? jb.Blo2 : jb.Blo;
    const uint32_t smb = smem_u32(smraw);
    const int lda = jb.lda, ldb = jb.ldb, kiters = jb.kiters;
    const bf16* gAhi = jb.Ahi + (size_t)m0 * lda;
    const bf16* gAlo = jb.Alo + (size_t)m0 * lda;
    const bf16* gBhi = Bh + (size_t)n0 * ldb;
    const bf16* gBlo = Bl + (size_t)n0 * ldb;

    DEF_LOAD_CHUNK(gAhi, gAlo, lda, gBhi, gBlo, ldb)

    if (blockIdx.x == 3) {
        // narrow tile: cols 192..199
        GEMM_CORE_N8(kiters)
#pragma unroll
        for (int half = 0; half < 2; half++) {
            const int row = m0 + wid * 16 + (lane >> 2) + half * 8;
            if (row >= jb.M) continue;
            int dst = row;
            float rs = 1.f;
            if (jb.epi == 3) {
                dst = (row < NEDGE) ? jb.eidx[NEDGE + row] : jb.ieidx[row];
                rs = jb.sc[row];
            }
#pragma unroll
            for (int jj = 0; jj < 2; jj++) {
                const int col = n0 + (lane & 3) * 2 + jj;   // 192..199 (< N)
                const float v = accn[half * 2 + jj];
                if (jb.epi == 0) {
                    jb.C[(size_t)row * jb.ldc + col] = v;
                } else if (jb.epi == 2) {
                    bf16 h, l; split2(v, h, l);
                    jb.Chi[(size_t)row * jb.ldcbf + col] = h;
                    jb.Clo[(size_t)row * jb.ldcbf + col] = l;
                } else if (jb.epi == 3) {
                    atomicAdd(&jb.C[(size_t)dst * jb.ldc + col], v * rs);
                } else {
                    atomicAdd(&jb.C[(size_t)row * jb.ldc + col], v);
                }
            }
        }
        return;
    }

    GEMM_CORE(kiters)

#pragma unroll
    for (int mb = 0; mb < 2; mb++) {
#pragma unroll
        for (int half = 0; half < 2; half++) {
            const int row = m0 + wm * 32 + mb * 16 + (lane >> 2) + half * 8;
            if (row >= jb.M) continue;
            int dst = row;
            float rs = 1.f;
            if (jb.epi == 3) {
                dst = (row < NEDGE) ? jb.eidx[NEDGE + row] : jb.ieidx[row];
                rs = jb.sc[row];
            }
#pragma unroll
            for (int nb = 0; nb < 4; nb++) {
#pragma unroll
                for (int jj = 0; jj < 2; jj++) {
                    const int col = n0 + wn * 32 + nb * 8 + (lane & 3) * 2 + jj;
                    const float v = acc[mb][nb][half * 2 + jj];
                    if (jb.epi == 0) {
                        if (col < jb.N) jb.C[(size_t)row * jb.ldc + col] = v;
                    } else if (jb.epi == 2) {
                        const float vv = (col < jb.N) ? v : 0.f;
                        bf16 h, l; split2(vv, h, l);
                        jb.Chi[(size_t)row * jb.ldcbf + col] = h;
                        jb.Clo[(size_t)row * jb.ldcbf + col] = l;
                    } else if (jb.epi == 3) {
                        if (col < jb.N)
                            atomicAdd(&jb.C[(size_t)dst * jb.ldc + col], v * rs);
                    } else {
                        if (col < jb.N)
                            atomicAdd(&jb.C[(size_t)row * jb.ldc + col], v);
                    }
                }
            }
        }
    }
}

// ---------------- FC GEMM (bias + bn2 + relu fused), bf16x3 ----------------
__global__ void __launch_bounds__(256, 2)
gemm_fc(const bf16* __restrict__ Ahi, const bf16* __restrict__ Alo, int lda,
        const bf16* __restrict__ Bhi, const bf16* __restrict__ Blo, int ldb, int kiters,
        float* __restrict__ C, int ldc, int M, int N,
        const float* __restrict__ bias, const float* __restrict__ g2,
        const float* __restrict__ b2) {
    extern __shared__ __align__(16) char smraw[];
    const int tid  = threadIdx.x;
    const int lane = tid & 31;
    const int wid  = tid >> 5;
    const int wm   = wid >> 1;
    const int wn   = wid & 1;
    const int m0   = blockIdx.y * 128;
    const int n0   = blockIdx.x * 64;

    const uint32_t smb = smem_u32(smraw);
    const bf16* gAhi = Ahi + (size_t)m0 * lda;
    const bf16* gAlo = Alo + (size_t)m0 * lda;
    const bf16* gBhi = Bhi + (size_t)n0 * ldb;
    const bf16* gBlo = Blo + (size_t)n0 * ldb;

    DEF_LOAD_CHUNK(gAhi, gAlo, lda, gBhi, gBlo, ldb)

    const float invs = rsqrtf(1.0f + 1e-5f);

    if (blockIdx.x == 3) {
        GEMM_CORE_N8(kiters)
#pragma unroll
        for (int half = 0; half < 2; half++) {
            const int row = m0 + wid * 16 + (lane >> 2) + half * 8;
            if (row >= M) continue;
#pragma unroll
            for (int jj = 0; jj < 2; jj++) {
                const int col = n0 + (lane & 3) * 2 + jj;
                float v = accn[half * 2 + jj];
                v = (v + bias[col]) * (g2[col] * invs) + b2[col];
                C[(size_t)row * ldc + col] = fmaxf(v, 0.f);
            }
        }
        return;
    }

    GEMM_CORE(kiters)

#pragma unroll
    for (int mb = 0; mb < 2; mb++) {
#pragma unroll
        for (int half = 0; half < 2; half++) {
            const int row = m0 + wm * 32 + mb * 16 + (lane >> 2) + half * 8;
            if (row >= M) continue;
#pragma unroll
            for (int nb = 0; nb < 4; nb++) {
#pragma unroll
                for (int jj = 0; jj < 2; jj++) {
                    const int col = n0 + wn * 32 + nb * 8 + (lane & 3) * 2 + jj;
                    if (col < N) {
                        float v = acc[mb][nb][half * 2 + jj];
                        v = (v + bias[col]) * (g2[col] * invs) + b2[col];
                        C[(size_t)row * ldc + col] = fmaxf(v, 0.f);
                    }
                }
            }
        }
    }
}

// ---------------- glue kernels ----------------
// also zeroes pad cols of t AND of BOTH rel ping-pong buffers (narrow tile never
// rewrites cols [200,256), so they must stay zero from init)
__global__ void k_init(const float* __restrict__ nodef, const float* __restrict__ ef,
                       const float* __restrict__ ief,
                       float* __restrict__ x, bf16* __restrict__ xhi, bf16* __restrict__ xlo,
                       bf16* __restrict__ rhi, bf16* __restrict__ rlo,
                       bf16* __restrict__ thi, bf16* __restrict__ tlo,
                       float* __restrict__ agg, float* __restrict__ deg) {
    int idx = blockIdx.x * blockDim.x + threadIdx.x;
    if (idx >= E2 * KPAD) return;
    int row = idx >> 8, d = idx & 255;
    float rv = 0.f;
    if (d < DDIM)
        rv = (row < NEDGE) ? ef[row * DDIM + d] : ief[(row - NEDGE) * DDIM + d];
    bf16 h, l; split2(rv, h, l);
    rhi[idx] = h; rlo[idx] = l;
    if (d >= DDIM) {
        thi[idx] = __float2bfloat16(0.f);
        tlo[idx] = __float2bfloat16(0.f);
        rhi[E2 * KPAD + idx] = __float2bfloat16(0.f);   // rel buffer 1 pads
        rlo[E2 * KPAD + idx] = __float2bfloat16(0.f);
    }
    if (row < MPADX) {
        float xv = (row < NNODES && d < DDIM) ? nodef[row * DDIM + d] : 0.f;
        split2(xv, h, l);
        xhi[idx] = h; xlo[idx] = l;
    }
    if (idx < NNODES * DDIM) { x[idx] = nodef[idx]; agg[idx] = 0.f; }
    if (idx < 2 * NNODES) deg[idx] = 0.f;
}

__global__ void k_deg(const int* __restrict__ ei, const int* __restrict__ iei,
                      float* __restrict__ deg) {
    int e = blockIdx.x * blockDim.x + threadIdx.x;
    if (e < NEDGE) {
        atomicAdd(&deg[ei[e]], 1.f);
        atomicAdd(&deg[NNODES + iei[e]], 1.f);
    }
}

__device__ __forceinline__ float dinvf(float v) { return v > 0.f ? rsqrtf(v) : 0.f; }

__global__ void k_norm(const int* __restrict__ ei, const int* __restrict__ iei,
                       const float* __restrict__ deg, float* __restrict__ sc) {
    int e = blockIdx.x * blockDim.x + threadIdx.x;
    if (e < NEDGE) {
        sc[e]         = dinvf(deg[ei[e]]) * dinvf(deg[ei[NEDGE + e]]);
        sc[NEDGE + e] = dinvf(deg[NNODES + iei[e]]) * dinvf(deg[NNODES + iei[NEDGE + e]]);
    }
}

// t = x[src] - rel, 2 elements per thread
__global__ void k_compose(const int* __restrict__ ei, const int* __restrict__ iei,
                          const float* __restrict__ x,
                          const bf16* __restrict__ rhi, const bf16* __restrict__ rlo,
                          bf16* __restrict__ thi, bf16* __restrict__ tlo) {
    int idx = blockIdx.x * blockDim.x + threadIdx.x;
    if (idx >= E2 * (DDIM / 2)) return;
    int row = idx / (DDIM / 2);
    int dp = (idx - row * (DDIM / 2)) * 2;
    int src = (row < NEDGE) ? ei[row] : iei[row - NEDGE];
    const float2 xv = *(const float2*)&x[src * DDIM + dp];
    const int ridx = row * KPAD + dp;
    const __nv_bfloat162 rh = *(const __nv_bfloat162*)&rhi[ridx];
    const __nv_bfloat162 rl = *(const __nv_bfloat162*)&rlo[ridx];
    float v0 = xv.x - (__bfloat162float(rh.x) + __bfloat162float(rl.x));
    float v1 = xv.y - (__bfloat162float(rh.y) + __bfloat162float(rl.y));
    bf16 h0, l0, h1, l1;
    split2(v0, h0, l0);
    split2(v1, h1, l1);
    *(__nv_bfloat162*)&thi[ridx] = __nv_bfloat162(h0, h1);
    *(__nv_bfloat162*)&tlo[ridx] = __nv_bfloat162(l0, l1);
}

// tanh activation, 2 elems/thread; re-zeroes agg
__global__ void k_act(const float* __restrict__ aggc, float* __restrict__ aggz,
                      const float* __restrict__ b, float* __restrict__ x,
                      bf16* __restrict__ xhi, bf16* __restrict__ xlo) {
    int idx = blockIdx.x * blockDim.x + threadIdx.x;
    if (idx >= NNODES * (DDIM / 2)) return;
    int row = idx / (DDIM / 2);
    int dp = (idx - row * (DDIM / 2)) * 2;
    const int gi = row * DDIM + dp;
    const float2 a = *(const float2*)&aggc[gi];
    *(float2*)&aggz[gi] = make_float2(0.f, 0.f);
    float v0 = tanhf(a.x * (1.0f / 3.0f) + b[dp]);
    float v1 = tanhf(a.y * (1.0f / 3.0f) + b[dp + 1]);
    *(float2*)&x[gi] = make_float2(v0, v1);
    bf16 h0, l0, h1, l1;
    split2(v0, h0, l0);
    split2(v1, h1, l1);
    const int ridx = row * KPAD + dp;
    *(__nv_bfloat162*)&xhi[ridx] = __nv_bfloat162(h0, h1);
    *(__nv_bfloat162*)&xlo[ridx] = __nv_bfloat162(l0, l1);
}

// weight prep: 24 matrices [200,200] -> transposed bf16 hi/lo [256,256]
__global__ void k_prep_wt(const float* __restrict__ Win, const float* __restrict__ Wout,
                          const float* __restrict__ Wloop, const float* __restrict__ Wrel,
                          bf16* __restrict__ hi, bf16* __restrict__ lo) {
    int idx = blockIdx.x * blockDim.x + threadIdx.x;
    if (idx >= 24 * KPAD * KPAD) return;
    int m = idx >> 16;
    int n = (idx >> 8) & 255;
    int k = idx & 255;
    float v = 0.f;
    if (n < DDIM && k < DDIM) {
        int t = m / 6, l = m % 6;
        const float* s = (t == 0) ? Win : (t == 1) ? Wout : (t == 2) ? Wloop : Wrel;
        v = s[l * DDIM * DDIM + k * DDIM + n];
    }
    bf16 h, l2; split2(v, h, l2);
    hi[idx] = h; lo[idx] = l2;
}

// fc_w [200, FLATSZ] -> bf16 hi/lo [256, FLATSZ] (rows >= 200 zero)
__global__ void k_prep_fc(const float* __restrict__ fcw,
                          bf16* __restrict__ hi, bf16* __restrict__ lo) {
    size_t idx = (size_t)blockIdx.x * blockDim.x + threadIdx.x;
    if (idx >= (size_t)256 * FLATSZ) return;
    int r = (int)(idx / FLATSZ);
    float v = (r < DDIM) ? fcw[idx] : 0.f;
    bf16 h, l; split2(v, h, l);
    hi[idx] = h; lo[idx] = l;
}

// ---------------- ConvE conv, FFMA2 filter-pair version ----------------
__global__ void __launch_bounds__(224, 2)
k_conv(const int* __restrict__ ei, const float* __restrict__ x,
       const bf16* __restrict__ rhi, const bf16* __restrict__ rlo,
       const float* __restrict__ conv_w, const float* __restrict__ conv_b,
       const float* __restrict__ bn0g, const float* __restrict__ bn0b,
       const float* __restrict__ bn1g, const float* __restrict__ bn1b,
       bf16* __restrict__ hfhi, bf16* __restrict__ hflo) {
    __shared__ __align__(16) u64 wp[48][50];
    __shared__ float img[400];
    __shared__ float cb[NFILT], s1[NFILT], b1[NFILT];

    const int e = blockIdx.x;
    const int tid = threadIdx.x;
    const float invs = rsqrtf(1.0f + 1e-5f);

    for (int i = tid; i < 48 * 50; i += 224) {
        int f2 = i / 50, t = i - f2 * 50;
        wp[f2][t] = (t < 49) ? pk2(conv_w[(2 * f2) * 49 + t], conv_w[(2 * f2 + 1) * 49 + t])
                             : 0ULL;
    }
    for (int i = tid; i < NFILT; i += 224) {
        cb[i] = conv_b[i];
        s1[i] = bn1g[i] * invs;
        b1[i] = bn1b[i];
    }
    const float sc0 = bn0g[0] * invs;
    const float bb0 = bn0b[0];
    const int sub = ei[e];
    for (int i = tid; i < 400; i += 224) {
        int ii = i / 20, jj = i - ii * 20;
        int k = ii * 10 + (jj >> 1);
        float v;
        if (jj & 1)
            v = __bfloat162float(rhi[e * KPAD + k]) + __bfloat162float(rlo[e * KPAD + k]);
        else
            v = x[sub * DDIM + k];
        img[i] = v * sc0 + bb0;
    }
    __syncthreads();

    if (tid < 196) {
        const int oi = tid / 14, oj = tid - oi * 14;
        u64 pd[50];
#pragma unroll
        for (int a = 0; a < 7; a++)
#pragma unroll
            for (int b = 0; b < 7; b++) {
                float p = img[(oi + a) * 20 + oj + b];
                pd[a * 7 + b] = pk2(p, p);
            }
        pd[49] = 0ULL;

        const size_t obase = (size_t)e * FLATSZ + tid;
        for (int f2 = 0; f2 < 48; f2++) {
            u64 acc = 0ULL;
#pragma unroll
            for (int t2 = 0; t2 < 25; t2++) {
                ulonglong2 w2 = *(const ulonglong2*)&wp[f2][2 * t2];
                fma2(acc, pd[2 * t2], w2.x);
                fma2(acc, pd[2 * t2 + 1], w2.y);
            }
            float2 vv = unpk(acc);
            const int f0 = 2 * f2, f1 = 2 * f2 + 1;
            float v0 = fmaxf((vv.x + cb[f0]) * s1[f0] + b1[f0], 0.f);
            float v1 = fmaxf((vv.y + cb[f1]) * s1[f1] + b1[f1], 0.f);
            bf16 h, l;
            split2(v0, h, l);
            hfhi[obase + (size_t)f0 * 196] = h; hflo[obase + (size_t)f0 * 196] = l;
            split2(v1, h, l);
            hfhi[obase + (size_t)f1 * 196] = h; hflo[obase + (size_t)f1 * 196] = l;
        }
    }
}

// ---------------- final tiny FC ----------------
__global__ void k_fc1(const float* __restrict__ h2, const float* __restrict__ fc1w,
                      const float* __restrict__ fc1b, float* __restrict__ out) {
    int idx = blockIdx.x * blockDim.x + threadIdx.x;
    if (idx < NEDGE * NCLASS) {
        int e = idx / NCLASS, c = idx - e * NCLASS;
        const float* h = h2 + e * DDIM;
        const float* w = fc1w + c * DDIM;
        float s = fc1b[c];
#pragma unroll 4
        for (int k = 0; k < DDIM; k++) s += h[k] * w[k];
        out[idx] = s;
    }
}

// ---------------- host launcher ----------------
extern "C" void kernel_launch(void* const* d_in, const int* in_sizes, int n_in,
                              void* d_out, int out_size) {
    const float* nodef = (const float*)d_in[0];
    const float* ef    = (const float*)d_in[1];
    const float* ief   = (const float*)d_in[2];
    const float* Win   = (const float*)d_in[3];
    const float* Wout  = (const float*)d_in[4];
    const float* Wloop = (const float*)d_in[5];
    const float* Wrel  = (const float*)d_in[6];
    const float* bgcn  = (const float*)d_in[7];
    const float* bn0g  = (const float*)d_in[8];
    const float* bn0b  = (const float*)d_in[9];
    const float* convw = (const float*)d_in[10];
    const float* convb = (const float*)d_in[11];
    const float* bn1g  = (const float*)d_in[12];
    const float* bn1b  = (const float*)d_in[13];
    const float* fcw   = (const float*)d_in[14];
    const float* fcb   = (const float*)d_in[15];
    const float* bn2g  = (const float*)d_in[16];
    const float* bn2b  = (const float*)d_in[17];
    const float* fc1w  = (const float*)d_in[18];
    const float* fc1b  = (const float*)d_in[19];
    const int*   ei    = (const int*)d_in[20];
    const int*   iei   = (const int*)d_in[21];
    float* out = (float*)d_out;

    float *px, *pagg, *pdeg, *psc, *ph2;
    bf16 *pxhi, *pxlo, *prhi0, *prlo0, *pthi, *ptlo, *phfhi, *phflo, *pwthi, *pwtlo, *pfchi, *pfclo;
    cudaGetSymbolAddress((void**)&px,    g_x);
    cudaGetSymbolAddress((void**)&pxhi,  g_xhi);
    cudaGetSymbolAddress((void**)&pxlo,  g_xlo);
    cudaGetSymbolAddress((void**)&prhi0, g_relhi);
    cudaGetSymbolAddress((void**)&prlo0, g_rello);
    cudaGetSymbolAddress((void**)&pthi,  g_thi);
    cudaGetSymbolAddress((void**)&ptlo,  g_tlo);
    cudaGetSymbolAddress((void**)&pagg,  g_agg);
    cudaGetSymbolAddress((void**)&pdeg,  g_deg);
    cudaGetSymbolAddress((void**)&psc,   g_scale);
    cudaGetSymbolAddress((void**)&phfhi, g_hfhi);
    cudaGetSymbolAddress((void**)&phflo, g_hflo);
    cudaGetSymbolAddress((void**)&ph2,   g_h2);
    cudaGetSymbolAddress((void**)&pwthi, g_wthi);
    cudaGetSymbolAddress((void**)&pwtlo, g_wtlo);
    cudaGetSymbolAddress((void**)&pfchi, g_fchi);
    cudaGetSymbolAddress((void**)&pfclo, g_fclo);

    const int GEMM_SMEM = 2 * STGBYTES;
    cudaFuncSetAttribute(gemm_multi, cudaFuncAttributeMaxDynamicSharedMemorySize, GEMM_SMEM);
    cudaFuncSetAttribute(gemm_fc,    cudaFuncAttributeMaxDynamicSharedMemorySize, GEMM_SMEM);

    const int RELSZ = E2 * KPAD;
    const int WMAT = KPAD * KPAD;
    const int NONE_SW = 0x40000000;

    auto make_jobs = [&](int l, int cur, GemmJob& j0, GemmJob& j1, GemmJob& j2) {
        bf16* rhi_c = prhi0 + cur * RELSZ;
        bf16* rlo_c = prlo0 + cur * RELSZ;
        bf16* rhi_n = prhi0 + (1 - cur) * RELSZ;
        bf16* rlo_n = prlo0 + (1 - cur) * RELSZ;
        j0 = { pthi, ptlo, KPAD,
               pwthi + (0 * 6 + l) * WMAT, pwtlo + (0 * 6 + l) * WMAT,
               pwthi + (1 * 6 + l) * WMAT, pwtlo + (1 * 6 + l) * WMAT, NEDGE,
               KPAD, KPAD / 64, E2 / 128,
               pagg, DDIM, E2, DDIM, nullptr, nullptr, 0, ei, iei, psc, 3 };
        j1 = { pxhi, pxlo, KPAD,
               pwthi + (2 * 6 + l) * WMAT, pwtlo + (2 * 6 + l) * WMAT,
               pwthi + (2 * 6 + l) * WMAT, pwtlo + (2 * 6 + l) * WMAT, NONE_SW,
               KPAD, KPAD / 64, MPADX / 128,
               pagg, DDIM, NNODES, DDIM, nullptr, nullptr, 0,
               nullptr, nullptr, nullptr, 4 };
        j2 = { rhi_c, rlo_c, KPAD,
               pwthi + (3 * 6 + l) * WMAT, pwtlo + (3 * 6 + l) * WMAT,
               pwthi + (3 * 6 + l) * WMAT, pwtlo + (3 * 6 + l) * WMAT, NONE_SW,
               KPAD, KPAD / 64, E2 / 128,
               nullptr, 0, E2, DDIM, rhi_n, rlo_n, KPAD,
               nullptr, nullptr, nullptr, 2 };
    };

    k_init<<<(E2 * KPAD + 255) / 256, 256>>>(nodef, ef, ief, px, pxhi, pxlo,
                                             prhi0, prlo0, pthi, ptlo, pagg, pdeg);
    k_prep_wt<<<(24 * WMAT + 255) / 256, 256>>>(Win, Wout, Wloop, Wrel, pwthi, pwtlo);
    k_deg<<<(NEDGE + 255) / 256, 256>>>(ei, iei, pdeg);
    k_compose<<<(E2 * (DDIM / 2) + 255) / 256, 256>>>(ei, iei, px, prhi0, prlo0,
                                                      pthi, ptlo);
    k_norm<<<(NEDGE + 255) / 256, 256>>>(ei, iei, pdeg, psc);
    k_prep_fc<<<(int)(((size_t)256 * FLATSZ + 255) / 256), 256>>>(fcw, pfchi, pfclo);

    dim3 gMulti(4, 128, 3);
    int cur = 0;
    for (int l = 0; l < NLAYER; l++) {
        if (l > 0) {
            bf16* rhi_c = prhi0 + cur * RELSZ;
            bf16* rlo_c = prlo0 + cur * RELSZ;
            k_compose<<<(E2 * (DDIM / 2) + 255) / 256, 256>>>(ei, iei, px, rhi_c, rlo_c,
                                                              pthi, ptlo);
        }
        GemmJob j0, j1, j2;
        make_jobs(l, cur, j0, j1, j2);
        gemm_multi<<<gMulti, 256, GEMM_SMEM>>>(j0, j1, j2);
        k_act<<<(NNODES * (DDIM / 2) + 255) / 256, 256>>>(pagg, pagg, bgcn + l * DDIM,
                                                          px, pxhi, pxlo);
        cur ^= 1;
    }
    bf16* rhi_f = prhi0 + cur * RELSZ;
    bf16* rlo_f = prlo0 + cur * RELSZ;

    k_conv<<<NEDGE, 224>>>(ei, px, rhi_f, rlo_f, convw, convb,
                           bn0g, bn0b, bn1g, bn1b, phfhi, phflo);

    dim3 gFC(4, NEDGE / 128);   // x==3 is the narrow 8-col remainder tile
    gemm_fc<<<gFC, 256, GEMM_SMEM>>>(phfhi, phflo, FLATSZ, pfchi, pfclo,
                                     FLATSZ, FLATSZ / 64, ph2, DDIM, NEDGE, DDIM,
                                     fcb, bn2g, bn2b);

    k_fc1<<<(NEDGE * NCLASS + 255) / 256, 256>>>(ph2, fc1w, fc1b, out);
}

// round 15
// speedup vs baseline: 1.3975x; 1.3975x over previous
#include <cuda_runtime.h>
#include <cuda_bf16.h>
#include <cstdint>

typedef __nv_bfloat16 bf16;
typedef unsigned long long u64;

// ---------------- problem constants ----------------
#define NNODES 5000
#define NEDGE  8192
#define DDIM   200
#define NLAYER 6
#define NFILT  96
#define FLATSZ 18816      // 96*14*14 = 294*64
#define NCLASS 13

#define MPADX   5120
#define KPAD    256
#define E2      (2*NEDGE)

// ---------------- device scratch (static, no allocs) ----------------
__device__ __align__(256) float g_x[NNODES * DDIM];
__device__ __align__(256) bf16  g_xhi[MPADX * KPAD], g_xlo[MPADX * KPAD];
__device__ __align__(256) bf16  g_relhi[2][E2 * KPAD], g_rello[2][E2 * KPAD];
__device__ __align__(256) bf16  g_thi[E2 * KPAD], g_tlo[E2 * KPAD];
__device__ __align__(256) float g_agg[NNODES * DDIM];
__device__ __align__(256) float g_deg[2 * NNODES];
__device__ __align__(256) float g_scale[2 * NEDGE];
__device__ __align__(256) bf16  g_hfhi[(size_t)NEDGE * FLATSZ], g_hflo[(size_t)NEDGE * FLATSZ];
__device__ __align__(256) float g_h2[NEDGE * DDIM];
__device__ __align__(256) bf16  g_wthi[24 * KPAD * KPAD], g_wtlo[24 * KPAD * KPAD];
__device__ __align__(256) bf16  g_fchi[256 * FLATSZ], g_fclo[256 * FLATSZ];

// ---------------- fp32x2 / bf16 helpers ----------------
__device__ __forceinline__ void fma2(u64& d, u64 a, u64 b) {
    asm("fma.rn.f32x2 %0, %1, %2, %0;" : "+l"(d) : "l"(a), "l"(b));
}
__device__ __forceinline__ float2 unpk(u64 v) {
    float2 r; asm("mov.b64 {%0, %1}, %2;" : "=f"(r.x), "=f"(r.y) : "l"(v)); return r;
}
__device__ __forceinline__ u64 pk2(float a, float b) {
    u64 r; asm("mov.b64 %0, {%1, %2};" : "=l"(r) : "f"(a), "f"(b)); return r;
}
__device__ __forceinline__ void split2(float v, bf16& h, bf16& l) {
    h = __float2bfloat16(v);
    l = __float2bfloat16(v - __bfloat162float(h));
}

// ---------------- mma.sync / ldmatrix / cp.async helpers ----------------
__device__ __forceinline__ uint32_t smem_u32(const void* p) {
    uint32_t a;
    asm("{ .reg .u64 t; cvta.to.shared.u64 t, %1; cvt.u32.u64 %0, t; }" : "=r"(a) : "l"(p));
    return a;
}
__device__ __forceinline__ void ldm4(uint32_t addr, uint32_t* r) {
    asm volatile("ldmatrix.sync.aligned.m8n8.x4.shared.b16 {%0,%1,%2,%3}, [%4];"
                 : "=r"(r[0]), "=r"(r[1]), "=r"(r[2]), "=r"(r[3]) : "r"(addr));
}
__device__ __forceinline__ void ldm2(uint32_t addr, uint32_t* r) {
    asm volatile("ldmatrix.sync.aligned.m8n8.x2.shared.b16 {%0,%1}, [%2];"
                 : "=r"(r[0]), "=r"(r[1]) : "r"(addr));
}
__device__ __forceinline__ void mma16816(float* c, const uint32_t* a,
                                         uint32_t b0, uint32_t b1) {
    asm volatile(
        "mma.sync.aligned.m16n8k16.row.col.f32.bf16.bf16.f32 "
        "{%0,%1,%2,%3}, {%4,%5,%6,%7}, {%8,%9}, {%0,%1,%2,%3};"
        : "+f"(c[0]), "+f"(c[1]), "+f"(c[2]), "+f"(c[3])
        : "r"(a[0]), "r"(a[1]), "r"(a[2]), "r"(a[3]), "r"(b0), "r"(b1));
}
#define CPA16(dst, src) \
    asm volatile("cp.async.cg.shared.global [%0], [%1], 16;" :: "r"(dst), "l"(src) : "memory")
#define CPA_COMMIT() asm volatile("cp.async.commit_group;" ::: "memory")

// ------- GEMM core: CTA tile 128x64, K-chunk 64, 8 warps (4m x 2n), 2 CTAs/SM -------
#define STGBYTES 55296
#define ALO_OFF  18432
#define BHI_OFF  36864
#define BLO_OFF  46080

struct GemmJob {
    const bf16 *Ahi, *Alo; int lda;
    const bf16 *Bhi, *Blo, *Bhi2, *Blo2; int mswitch;
    int ldb, kiters, mtiles;
    float* C; int ldc;
    int M, N;
    bf16 *Chi, *Clo; int ldcbf;
    const int *eidx, *ieidx;
    const float* sc;
    int epi;  // 0 plain | 2 bf16 split | 3 atomic scatter scaled | 4 atomicAdd
};

// shared staging loads (identical for full and narrow instantiations)
#define DEF_LOAD_CHUNK(gAhi_, gAlo_, lda_, gBhi_, gBlo_, ldb_)                             \
    auto load_chunk = [&](int kc, int s) {                                                  \
        const uint32_t sb = smb + s * STGBYTES;                                             \
        const size_t koff = (size_t)kc * 64;                                                \
        _Pragma("unroll") for (int jv = 0; jv < 4; jv++) {                                  \
            const int id = tid + jv * 256;                                                  \
            const int r = id >> 3, c = id & 7;                                              \
            const uint32_t off = (uint32_t)(r * 144 + c * 16);                              \
            const size_t src = (size_t)r * (lda_) + koff + c * 8;                           \
            CPA16(sb + off,           (gAhi_) + src);                                       \
            CPA16(sb + ALO_OFF + off, (gAlo_) + src);                                       \
        }                                                                                   \
        _Pragma("unroll") for (int jv = 0; jv < 2; jv++) {                                  \
            const int id = tid + jv * 256;                                                  \
            const int r = id >> 3, c = id & 7;                                              \
            const uint32_t off = (uint32_t)(r * 144 + c * 16);                              \
            const size_t src = (size_t)r * (ldb_) + koff + c * 8;                           \
            CPA16(sb + BHI_OFF + off, (gBhi_) + src);                                       \
            CPA16(sb + BLO_OFF + off, (gBlo_) + src);                                      \
        }                                                                                   \
        CPA_COMMIT();                                                                       \
    };

// full 128x64 tile mainloop (round-4-validated fragment mapping)
#define GEMM_CORE(kiters_)                                                                 \
    float acc[2][4][4];                                                                     \
    _Pragma("unroll") for (int mb = 0; mb < 2; mb++)                                        \
    _Pragma("unroll") for (int nb = 0; nb < 4; nb++)                                        \
    _Pragma("unroll") for (int v = 0; v < 4; v++) acc[mb][nb][v] = 0.f;                     \
    const uint32_t aRow = (uint32_t)((wm * 32 + (lane & 15)) * 144 + (lane >> 4) * 16);     \
    const int bg = lane >> 3;                                                               \
    const uint32_t bRow = (uint32_t)((wn * 32 + ((bg >> 1) * 8) + (lane & 7)) * 144         \
                                     + (bg & 1) * 16);                                      \
    load_chunk(0, 0);                                                                       \
    load_chunk(1, 1);                                                                       \
    for (int i = 0; i < (kiters_); i++) {                                                   \
        const int s = i & 1;                                                                \
        if (i + 1 < (kiters_)) asm volatile("cp.async.wait_group 1;" ::: "memory");         \
        else                   asm volatile("cp.async.wait_group 0;" ::: "memory");         \
        __syncthreads();                                                                    \
        const uint32_t sb = smb + s * STGBYTES;                                             \
        _Pragma("unroll") for (int ks = 0; ks < 4; ks++) {                                  \
            uint32_t ah[2][4], al[2][4];                                                    \
            _Pragma("unroll") for (int mb = 0; mb < 2; mb++) {                              \
                const uint32_t a = sb + aRow + (uint32_t)(mb * 16 * 144 + ks * 32);         \
                ldm4(a, ah[mb]);                                                            \
                ldm4(a + ALO_OFF, al[mb]);                                                  \
            }                                                                               \
            _Pragma("unroll") for (int p = 0; p < 2; p++) {                                 \
                uint32_t bh[4], bl[4];                                                      \
                const uint32_t b = sb + BHI_OFF + bRow + (uint32_t)(p * 16 * 144 + ks * 32);\
                ldm4(b, bh);                                                                \
                ldm4(b + (BLO_OFF - BHI_OFF), bl);                                          \
                _Pragma("unroll") for (int mb = 0; mb < 2; mb++)                            \
                _Pragma("unroll") for (int half = 0; half < 2; half++) {                    \
                    const int nb = p * 2 + half;                                            \
                    const int o = half * 2;                                                 \
                    mma16816(acc[mb][nb], ah[mb], bh[o], bh[o + 1]);                        \
                    mma16816(acc[mb][nb], al[mb], bh[o], bh[o + 1]);                        \
                    mma16816(acc[mb][nb], ah[mb], bl[o], bl[o + 1]);                        \
                }                                                                           \
            }                                                                               \
        }                                                                                   \
        __syncthreads();                                                                    \
        if (i + 2 < (kiters_)) load_chunk(i + 2, s);                                        \
    }

// narrow 128x8 tile mainloop: warp w -> rows w*16..w*16+15, cols 0..7 of the tile.
#define GEMM_CORE_N8(kiters_)                                                              \
    float accn[4] = {0.f, 0.f, 0.f, 0.f};                                                   \
    const uint32_t aRowN = (uint32_t)((wid * 16 + (lane & 15)) * 144 + (lane >> 4) * 16);   \
    const uint32_t bRowN = (uint32_t)((lane & 7) * 144 + ((lane >> 3) & 1) * 16);           \
    load_chunk(0, 0);                                                                       \
    load_chunk(1, 1);                                                                       \
    for (int i = 0; i < (kiters_); i++) {                                                   \
        const int s = i & 1;                                                                \
        if (i + 1 < (kiters_)) asm volatile("cp.async.wait_group 1;" ::: "memory");         \
        else                   asm volatile("cp.async.wait_group 0;" ::: "memory");         \
        __syncthreads();                                                                    \
        const uint32_t sb = smb + s * STGBYTES;                                             \
        _Pragma("unroll") for (int ks = 0; ks < 4; ks++) {                                  \
            uint32_t ahn[4], aln[4], bhn[2], bln[2];                                        \
            const uint32_t a = sb + aRowN + (uint32_t)(ks * 32);                            \
            ldm4(a, ahn);                                                                   \
            ldm4(a + ALO_OFF, aln);                                                         \
            const uint32_t b = sb + BHI_OFF + bRowN + (uint32_t)(ks * 32);                  \
            ldm2(b, bhn);                                                                   \
            ldm2(b + (BLO_OFF - BHI_OFF), bln);                                             \
            mma16816(accn, ahn, bhn[0], bhn[1]);                                            \
            mma16816(accn, aln, bhn[0], bhn[1]);                                            \
            mma16816(accn, ahn, bln[0], bln[1]);                                            \
        }                                                                                   \
        __syncthreads();                                                                    \
        if (i + 2 < (kiters_)) load_chunk(i + 2, s);                                        \
    }

// ---------------- merged per-layer GEMM; NARROW selects the instantiated path ----------
template <int NARROW>
__global__ void __launch_bounds__(256, 2)
gemm_multi(GemmJob j0, GemmJob j1, GemmJob j2) {
    const GemmJob jb = (blockIdx.z == 0) ? j0 : (blockIdx.z == 1) ? j1 : j2;
    if ((int)blockIdx.y >= jb.mtiles) return;

    extern __shared__ __align__(16) char smraw[];
    const int tid  = threadIdx.x;
    const int lane = tid & 31;
    const int wid  = tid >> 5;
    const int wm   = wid >> 1;
    const int wn   = wid & 1;
    const int m0   = blockIdx.y * 128;
    const int n0   = NARROW ? 192 : blockIdx.x * 64;

    const bf16* Bh = (m0 >= jb.mswitch) ? jb.Bhi2 : jb.Bhi;
    const bf16* Bl = (m0 >= jb.mswitch) ? jb.Blo2 : jb.Blo;
    const uint32_t smb = smem_u32(smraw);
    const int lda = jb.lda, ldb = jb.ldb, kiters = jb.kiters;
    const bf16* gAhi = jb.Ahi + (size_t)m0 * lda;
    const bf16* gAlo = jb.Alo + (size_t)m0 * lda;
    const bf16* gBhi = Bh + (size_t)n0 * ldb;
    const bf16* gBlo = Bl + (size_t)n0 * ldb;

    DEF_LOAD_CHUNK(gAhi, gAlo, lda, gBhi, gBlo, ldb)

    if (NARROW) {
        GEMM_CORE_N8(kiters)
#pragma unroll
        for (int half = 0; half < 2; half++) {
            const int row = m0 + wid * 16 + (lane >> 2) + half * 8;
            if (row >= jb.M) continue;
            int dst = row;
            float rs = 1.f;
            if (jb.epi == 3) {
                dst = (row < NEDGE) ? jb.eidx[NEDGE + row] : jb.ieidx[row];
                rs = jb.sc[row];
            }
#pragma unroll
            for (int jj = 0; jj < 2; jj++) {
                const int col = n0 + (lane & 3) * 2 + jj;   // 192..199 (< N)
                const float v = accn[half * 2 + jj];
                if (jb.epi == 0) {
                    jb.C[(size_t)row * jb.ldc + col] = v;
                } else if (jb.epi == 2) {
                    bf16 h, l; split2(v, h, l);
                    jb.Chi[(size_t)row * jb.ldcbf + col] = h;
                    jb.Clo[(size_t)row * jb.ldcbf + col] = l;
                } else if (jb.epi == 3) {
                    atomicAdd(&jb.C[(size_t)dst * jb.ldc + col], v * rs);
                } else {
                    atomicAdd(&jb.C[(size_t)row * jb.ldc + col], v);
                }
            }
        }
        return;
    }

    GEMM_CORE(kiters)

#pragma unroll
    for (int mb = 0; mb < 2; mb++) {
#pragma unroll
        for (int half = 0; half < 2; half++) {
            const int row = m0 + wm * 32 + mb * 16 + (lane >> 2) + half * 8;
            if (row >= jb.M) continue;
            int dst = row;
            float rs = 1.f;
            if (jb.epi == 3) {
                dst = (row < NEDGE) ? jb.eidx[NEDGE + row] : jb.ieidx[row];
                rs = jb.sc[row];
            }
#pragma unroll
            for (int nb = 0; nb < 4; nb++) {
#pragma unroll
                for (int jj = 0; jj < 2; jj++) {
                    const int col = n0 + wn * 32 + nb * 8 + (lane & 3) * 2 + jj;
                    const float v = acc[mb][nb][half * 2 + jj];
                    if (jb.epi == 0) {
                        jb.C[(size_t)row * jb.ldc + col] = v;
                    } else if (jb.epi == 2) {
                        bf16 h, l; split2(v, h, l);
                        jb.Chi[(size_t)row * jb.ldcbf + col] = h;
                        jb.Clo[(size_t)row * jb.ldcbf + col] = l;
                    } else if (jb.epi == 3) {
                        atomicAdd(&jb.C[(size_t)dst * jb.ldc + col], v * rs);
                    } else {
                        atomicAdd(&jb.C[(size_t)row * jb.ldc + col], v);
                    }
                }
            }
        }
    }
}

// ---------------- FC GEMM (bias + bn2 + relu fused), bf16x3 ----------------
template <int NARROW>
__global__ void __launch_bounds__(256, 2)
gemm_fc(const bf16* __restrict__ Ahi, const bf16* __restrict__ Alo, int lda,
        const bf16* __restrict__ Bhi, const bf16* __restrict__ Blo, int ldb, int kiters,
        float* __restrict__ C, int ldc, int M, int N,
        const float* __restrict__ bias, const float* __restrict__ g2,
        const float* __restrict__ b2) {
    extern __shared__ __align__(16) char smraw[];
    const int tid  = threadIdx.x;
    const int lane = tid & 31;
    const int wid  = tid >> 5;
    const int wm   = wid >> 1;
    const int wn   = wid & 1;
    const int m0   = blockIdx.y * 128;
    const int n0   = NARROW ? 192 : blockIdx.x * 64;

    const uint32_t smb = smem_u32(smraw);
    const bf16* gAhi = Ahi + (size_t)m0 * lda;
    const bf16* gAlo = Alo + (size_t)m0 * lda;
    const bf16* gBhi = Bhi + (size_t)n0 * ldb;
    const bf16* gBlo = Blo + (size_t)n0 * ldb;

    DEF_LOAD_CHUNK(gAhi, gAlo, lda, gBhi, gBlo, ldb)

    const float invs = rsqrtf(1.0f + 1e-5f);

    if (NARROW) {
        GEMM_CORE_N8(kiters)
#pragma unroll
        for (int half = 0; half < 2; half++) {
            const int row = m0 + wid * 16 + (lane >> 2) + half * 8;
            if (row >= M) continue;
#pragma unroll
            for (int jj = 0; jj < 2; jj++) {
                const int col = n0 + (lane & 3) * 2 + jj;
                float v = accn[half * 2 + jj];
                v = (v + bias[col]) * (g2[col] * invs) + b2[col];
                C[(size_t)row * ldc + col] = fmaxf(v, 0.f);
            }
        }
        return;
    }

    GEMM_CORE(kiters)

#pragma unroll
    for (int mb = 0; mb < 2; mb++) {
#pragma unroll
        for (int half = 0; half < 2; half++) {
            const int row = m0 + wm * 32 + mb * 16 + (lane >> 2) + half * 8;
            if (row >= M) continue;
#pragma unroll
            for (int nb = 0; nb < 4; nb++) {
#pragma unroll
                for (int jj = 0; jj < 2; jj++) {
                    const int col = n0 + wn * 32 + nb * 8 + (lane & 3) * 2 + jj;
                    float v = acc[mb][nb][half * 2 + jj];
                    v = (v + bias[col]) * (g2[col] * invs) + b2[col];
                    C[(size_t)row * ldc + col] = fmaxf(v, 0.f);
                }
            }
        }
    }
}

// ---------------- glue kernels ----------------
// zeroes pad cols of t AND of BOTH rel ping-pong buffers (narrow tile never
// rewrites cols [200,256), so they must stay zero from init)
__global__ void k_init(const float* __restrict__ nodef, const float* __restrict__ ef,
                       const float* __restrict__ ief,
                       float* __restrict__ x, bf16* __restrict__ xhi, bf16* __restrict__ xlo,
                       bf16* __restrict__ rhi, bf16* __restrict__ rlo,
                       bf16* __restrict__ thi, bf16* __restrict__ tlo,
                       float* __restrict__ agg, float* __restrict__ deg) {
    int idx = blockIdx.x * blockDim.x + threadIdx.x;
    if (idx >= E2 * KPAD) return;
    int row = idx >> 8, d = idx & 255;
    float rv = 0.f;
    if (d < DDIM)
        rv = (row < NEDGE) ? ef[row * DDIM + d] : ief[(row - NEDGE) * DDIM + d];
    bf16 h, l; split2(rv, h, l);
    rhi[idx] = h; rlo[idx] = l;
    if (d >= DDIM) {
        thi[idx] = __float2bfloat16(0.f);
        tlo[idx] = __float2bfloat16(0.f);
        rhi[E2 * KPAD + idx] = __float2bfloat16(0.f);
        rlo[E2 * KPAD + idx] = __float2bfloat16(0.f);
    }
    if (row < MPADX) {
        float xv = (row < NNODES && d < DDIM) ? nodef[row * DDIM + d] : 0.f;
        split2(xv, h, l);
        xhi[idx] = h; xlo[idx] = l;
    }
    if (idx < NNODES * DDIM) { x[idx] = nodef[idx]; agg[idx] = 0.f; }
    if (idx < 2 * NNODES) deg[idx] = 0.f;
}

__global__ void k_deg(const int* __restrict__ ei, const int* __restrict__ iei,
                      float* __restrict__ deg) {
    int e = blockIdx.x * blockDim.x + threadIdx.x;
    if (e < NEDGE) {
        atomicAdd(&deg[ei[e]], 1.f);
        atomicAdd(&deg[NNODES + iei[e]], 1.f);
    }
}

__device__ __forceinline__ float dinvf(float v) { return v > 0.f ? rsqrtf(v) : 0.f; }

__global__ void k_norm(const int* __restrict__ ei, const int* __restrict__ iei,
                       const float* __restrict__ deg, float* __restrict__ sc) {
    int e = blockIdx.x * blockDim.x + threadIdx.x;
    if (e < NEDGE) {
        sc[e]         = dinvf(deg[ei[e]]) * dinvf(deg[ei[NEDGE + e]]);
        sc[NEDGE + e] = dinvf(deg[NNODES + iei[e]]) * dinvf(deg[NNODES + iei[NEDGE + e]]);
    }
}

// t = x[src] - rel, 2 elements per thread
__global__ void k_compose(const int* __restrict__ ei, const int* __restrict__ iei,
                          const float* __restrict__ x,
                          const bf16* __restrict__ rhi, const bf16* __restrict__ rlo,
                          bf16* __restrict__ thi, bf16* __restrict__ tlo) {
    int idx = blockIdx.x * blockDim.x + threadIdx.x;
    if (idx >= E2 * (DDIM / 2)) return;
    int row = idx / (DDIM / 2);
    int dp = (idx - row * (DDIM / 2)) * 2;
    int src = (row < NEDGE) ? ei[row] : iei[row - NEDGE];
    const float2 xv = *(const float2*)&x[src * DDIM + dp];
    const int ridx = row * KPAD + dp;
    const __nv_bfloat162 rh = *(const __nv_bfloat162*)&rhi[ridx];
    const __nv_bfloat162 rl = *(const __nv_bfloat162*)&rlo[ridx];
    float v0 = xv.x - (__bfloat162float(rh.x) + __bfloat162float(rl.x));
    float v1 = xv.y - (__bfloat162float(rh.y) + __bfloat162float(rl.y));
    bf16 h0, l0, h1, l1;
    split2(v0, h0, l0);
    split2(v1, h1, l1);
    *(__nv_bfloat162*)&thi[ridx] = __nv_bfloat162(h0, h1);
    *(__nv_bfloat162*)&tlo[ridx] = __nv_bfloat162(l0, l1);
}

// tanh activation, 2 elems/thread; re-zeroes agg
__global__ void k_act(const float* __restrict__ aggc, float* __restrict__ aggz,
                      const float* __restrict__ b, float* __restrict__ x,
                      bf16* __restrict__ xhi, bf16* __restrict__ xlo) {
    int idx = blockIdx.x * blockDim.x + threadIdx.x;
    if (idx >= NNODES * (DDIM / 2)) return;
    int row = idx / (DDIM / 2);
    int dp = (idx - row * (DDIM / 2)) * 2;
    const int gi = row * DDIM + dp;
    const float2 a = *(const float2*)&aggc[gi];
    *(float2*)&aggz[gi] = make_float2(0.f, 0.f);
    float v0 = tanhf(a.x * (1.0f / 3.0f) + b[dp]);
    float v1 = tanhf(a.y * (1.0f / 3.0f) + b[dp + 1]);
    *(float2*)&x[gi] = make_float2(v0, v1);
    bf16 h0, l0, h1, l1;
    split2(v0, h0, l0);
    split2(v1, h1, l1);
    const int ridx = row * KPAD + dp;
    *(__nv_bfloat162*)&xhi[ridx] = __nv_bfloat162(h0, h1);
    *(__nv_bfloat162*)&xlo[ridx] = __nv_bfloat162(l0, l1);
}

// weight prep: 24 matrices [200,200] -> transposed bf16 hi/lo [256,256]
__global__ void k_prep_wt(const float* __restrict__ Win, const float* __restrict__ Wout,
                          const float* __restrict__ Wloop, const float* __restrict__ Wrel,
                          bf16* __restrict__ hi, bf16* __restrict__ lo) {
    int idx = blockIdx.x * blockDim.x + threadIdx.x;
    if (idx >= 24 * KPAD * KPAD) return;
    int m = idx >> 16;
    int n = (idx >> 8) & 255;
    int k = idx & 255;
    float v = 0.f;
    if (n < DDIM && k < DDIM) {
        int t = m / 6, l = m % 6;
        const float* s = (t == 0) ? Win : (t == 1) ? Wout : (t == 2) ? Wloop : Wrel;
        v = s[l * DDIM * DDIM + k * DDIM + n];
    }
    bf16 h, l2; split2(v, h, l2);
    hi[idx] = h; lo[idx] = l2;
}

// fc_w [200, FLATSZ] -> bf16 hi/lo [256, FLATSZ] (rows >= 200 zero)
__global__ void k_prep_fc(const float* __restrict__ fcw,
                          bf16* __restrict__ hi, bf16* __restrict__ lo) {
    size_t idx = (size_t)blockIdx.x * blockDim.x + threadIdx.x;
    if (idx >= (size_t)256 * FLATSZ) return;
    int r = (int)(idx / FLATSZ);
    float v = (r < DDIM) ? fcw[idx] : 0.f;
    bf16 h, l; split2(v, h, l);
    hi[idx] = h; lo[idx] = l;
}

// ---------------- ConvE conv, FFMA2 filter-pair version ----------------
__global__ void __launch_bounds__(224, 2)
k_conv(const int* __restrict__ ei, const float* __restrict__ x,
       const bf16* __restrict__ rhi, const bf16* __restrict__ rlo,
       const float* __restrict__ conv_w, const float* __restrict__ conv_b,
       const float* __restrict__ bn0g, const float* __restrict__ bn0b,
       const float* __restrict__ bn1g, const float* __restrict__ bn1b,
       bf16* __restrict__ hfhi, bf16* __restrict__ hflo) {
    __shared__ __align__(16) u64 wp[48][50];
    __shared__ float img[400];
    __shared__ float cb[NFILT], s1[NFILT], b1[NFILT];

    const int e = blockIdx.x;
    const int tid = threadIdx.x;
    const float invs = rsqrtf(1.0f + 1e-5f);

    for (int i = tid; i < 48 * 50; i += 224) {
        int f2 = i / 50, t = i - f2 * 50;
        wp[f2][t] = (t < 49) ? pk2(conv_w[(2 * f2) * 49 + t], conv_w[(2 * f2 + 1) * 49 + t])
                             : 0ULL;
    }
    for (int i = tid; i < NFILT; i += 224) {
        cb[i] = conv_b[i];
        s1[i] = bn1g[i] * invs;
        b1[i] = bn1b[i];
    }
    const float sc0 = bn0g[0] * invs;
    const float bb0 = bn0b[0];
    const int sub = ei[e];
    for (int i = tid; i < 400; i += 224) {
        int ii = i / 20, jj = i - ii * 20;
        int k = ii * 10 + (jj >> 1);
        float v;
        if (jj & 1)
            v = __bfloat162float(rhi[e * KPAD + k]) + __bfloat162float(rlo[e * KPAD + k]);
        else
            v = x[sub * DDIM + k];
        img[i] = v * sc0 + bb0;
    }
    __syncthreads();

    if (tid < 196) {
        const int oi = tid / 14, oj = tid - oi * 14;
        u64 pd[50];
#pragma unroll
        for (int a = 0; a < 7; a++)
#pragma unroll
            for (int b = 0; b < 7; b++) {
                float p = img[(oi + a) * 20 + oj + b];
                pd[a * 7 + b] = pk2(p, p);
            }
        pd[49] = 0ULL;

        const size_t obase = (size_t)e * FLATSZ + tid;
        for (int f2 = 0; f2 < 48; f2++) {
            u64 acc = 0ULL;
#pragma unroll
            for (int t2 = 0; t2 < 25; t2++) {
                ulonglong2 w2 = *(const ulonglong2*)&wp[f2][2 * t2];
                fma2(acc, pd[2 * t2], w2.x);
                fma2(acc, pd[2 * t2 + 1], w2.y);
            }
            float2 vv = unpk(acc);
            const int f0 = 2 * f2, f1 = 2 * f2 + 1;
            float v0 = fmaxf((vv.x + cb[f0]) * s1[f0] + b1[f0], 0.f);
            float v1 = fmaxf((vv.y + cb[f1]) * s1[f1] + b1[f1], 0.f);
            bf16 h, l;
            split2(v0, h, l);
            hfhi[obase + (size_t)f0 * 196] = h; hflo[obase + (size_t)f0 * 196] = l;
            split2(v1, h, l);
            hfhi[obase + (size_t)f1 * 196] = h; hflo[obase + (size_t)f1 * 196] = l;
        }
    }
}

// ---------------- final tiny FC ----------------
__global__ void k_fc1(const float* __restrict__ h2, const float* __restrict__ fc1w,
                      const float* __restrict__ fc1b, float* __restrict__ out) {
    int idx = blockIdx.x * blockDim.x + threadIdx.x;
    if (idx < NEDGE * NCLASS) {
        int e = idx / NCLASS, c = idx - e * NCLASS;
        const float* h = h2 + e * DDIM;
        const float* w = fc1w + c * DDIM;
        float s = fc1b[c];
#pragma unroll 4
        for (int k = 0; k < DDIM; k++) s += h[k] * w[k];
        out[idx] = s;
    }
}

// ---------------- host launcher ----------------
extern "C" void kernel_launch(void* const* d_in, const int* in_sizes, int n_in,
                              void* d_out, int out_size) {
    const float* nodef = (const float*)d_in[0];
    const float* ef    = (const float*)d_in[1];
    const float* ief   = (const float*)d_in[2];
    const float* Win   = (const float*)d_in[3];
    const float* Wout  = (const float*)d_in[4];
    const float* Wloop = (const float*)d_in[5];
    const float* Wrel  = (const float*)d_in[6];
    const float* bgcn  = (const float*)d_in[7];
    const float* bn0g  = (const float*)d_in[8];
    const float* bn0b  = (const float*)d_in[9];
    const float* convw = (const float*)d_in[10];
    const float* convb = (const float*)d_in[11];
    const float* bn1g  = (const float*)d_in[12];
    const float* bn1b  = (const float*)d_in[13];
    const float* fcw   = (const float*)d_in[14];
    const float* fcb   = (const float*)d_in[15];
    const float* bn2g  = (const float*)d_in[16];
    const float* bn2b  = (const float*)d_in[17];
    const float* fc1w  = (const float*)d_in[18];
    const float* fc1b  = (const float*)d_in[19];
    const int*   ei    = (const int*)d_in[20];
    const int*   iei   = (const int*)d_in[21];
    float* out = (float*)d_out;

    float *px, *pagg, *pdeg, *psc, *ph2;
    bf16 *pxhi, *pxlo, *prhi0, *prlo0, *pthi, *ptlo, *phfhi, *phflo, *pwthi, *pwtlo, *pfchi, *pfclo;
    cudaGetSymbolAddress((void**)&px,    g_x);
    cudaGetSymbolAddress((void**)&pxhi,  g_xhi);
    cudaGetSymbolAddress((void**)&pxlo,  g_xlo);
    cudaGetSymbolAddress((void**)&prhi0, g_relhi);
    cudaGetSymbolAddress((void**)&prlo0, g_rello);
    cudaGetSymbolAddress((void**)&pthi,  g_thi);
    cudaGetSymbolAddress((void**)&ptlo,  g_tlo);
    cudaGetSymbolAddress((void**)&pagg,  g_agg);
    cudaGetSymbolAddress((void**)&pdeg,  g_deg);
    cudaGetSymbolAddress((void**)&psc,   g_scale);
    cudaGetSymbolAddress((void**)&phfhi, g_hfhi);
    cudaGetSymbolAddress((void**)&phflo, g_hflo);
    cudaGetSymbolAddress((void**)&ph2,   g_h2);
    cudaGetSymbolAddress((void**)&pwthi, g_wthi);
    cudaGetSymbolAddress((void**)&pwtlo, g_wtlo);
    cudaGetSymbolAddress((void**)&pfchi, g_fchi);
    cudaGetSymbolAddress((void**)&pfclo, g_fclo);

    const int GEMM_SMEM = 2 * STGBYTES;
    cudaFuncSetAttribute(gemm_multi<0>, cudaFuncAttributeMaxDynamicSharedMemorySize, GEMM_SMEM);
    cudaFuncSetAttribute(gemm_multi<1>, cudaFuncAttributeMaxDynamicSharedMemorySize, GEMM_SMEM);
    cudaFuncSetAttribute(gemm_fc<0>,    cudaFuncAttributeMaxDynamicSharedMemorySize, GEMM_SMEM);
    cudaFuncSetAttribute(gemm_fc<1>,    cudaFuncAttributeMaxDynamicSharedMemorySize, GEMM_SMEM);

    const int RELSZ = E2 * KPAD;
    const int WMAT = KPAD * KPAD;
    const int NONE_SW = 0x40000000;

    auto make_jobs = [&](int l, int cur, GemmJob& j0, GemmJob& j1, GemmJob& j2) {
        bf16* rhi_c = prhi0 + cur * RELSZ;
        bf16* rlo_c = prlo0 + cur * RELSZ;
        bf16* rhi_n = prhi0 + (1 - cur) * RELSZ;
        bf16* rlo_n = prlo0 + (1 - cur) * RELSZ;
        j0 = { pthi, ptlo, KPAD,
               pwthi + (0 * 6 + l) * WMAT, pwtlo + (0 * 6 + l) * WMAT,
               pwthi + (1 * 6 + l) * WMAT, pwtlo + (1 * 6 + l) * WMAT, NEDGE,
               KPAD, KPAD / 64, E2 / 128,
               pagg, DDIM, E2, DDIM, nullptr, nullptr, 0, ei, iei, psc, 3 };
        j1 = { pxhi, pxlo, KPAD,
               pwthi + (2 * 6 + l) * WMAT, pwtlo + (2 * 6 + l) * WMAT,
               pwthi + (2 * 6 + l) * WMAT, pwtlo + (2 * 6 + l) * WMAT, NONE_SW,
               KPAD, KPAD / 64, MPADX / 128,
               pagg, DDIM, NNODES, DDIM, nullptr, nullptr, 0,
               nullptr, nullptr, nullptr, 4 };
        j2 = { rhi_c, rlo_c, KPAD,
               pwthi + (3 * 6 + l) * WMAT, pwtlo + (3 * 6 + l) * WMAT,
               pwthi + (3 * 6 + l) * WMAT, pwtlo + (3 * 6 + l) * WMAT, NONE_SW,
               KPAD, KPAD / 64, E2 / 128,
               nullptr, 0, E2, DDIM, rhi_n, rlo_n, KPAD,
               nullptr, nullptr, nullptr, 2 };
    };

    k_init<<<(E2 * KPAD + 255) / 256, 256>>>(nodef, ef, ief, px, pxhi, pxlo,
                                             prhi0, prlo0, pthi, ptlo, pagg, pdeg);
    k_prep_wt<<<(24 * WMAT + 255) / 256, 256>>>(Win, Wout, Wloop, Wrel, pwthi, pwtlo);
    k_deg<<<(NEDGE + 255) / 256, 256>>>(ei, iei, pdeg);
    k_compose<<<(E2 * (DDIM / 2) + 255) / 256, 256>>>(ei, iei, px, prhi0, prlo0,
                                                      pthi, ptlo);
    k_norm<<<(NEDGE + 255) / 256, 256>>>(ei, iei, pdeg, psc);
    k_prep_fc<<<(int)(((size_t)256 * FLATSZ + 255) / 256), 256>>>(fcw, pfchi, pfclo);

    dim3 gMultiF(3, 128, 3);   // full 64-col tiles: cols 0..191
    dim3 gMultiN(1, 128, 3);   // narrow 8-col tile: cols 192..199
    int cur = 0;
    for (int l = 0; l < NLAYER; l++) {
        if (l > 0) {
            bf16* rhi_c = prhi0 + cur * RELSZ;
            bf16* rlo_c = prlo0 + cur * RELSZ;
            k_compose<<<(E2 * (DDIM / 2) + 255) / 256, 256>>>(ei, iei, px, rhi_c, rlo_c,
                                                              pthi, ptlo);
        }
        GemmJob j0, j1, j2;
        make_jobs(l, cur, j0, j1, j2);
        gemm_multi<0><<<gMultiF, 256, GEMM_SMEM>>>(j0, j1, j2);
        gemm_multi<1><<<gMultiN, 256, GEMM_SMEM>>>(j0, j1, j2);
        k_act<<<(NNODES * (DDIM / 2) + 255) / 256, 256>>>(pagg, pagg, bgcn + l * DDIM,
                                                          px, pxhi, pxlo);
        cur ^= 1;
    }
    bf16* rhi_f = prhi0 + cur * RELSZ;
    bf16* rlo_f = prlo0 + cur * RELSZ;

    k_conv<<<NEDGE, 224>>>(ei, px, rhi_f, rlo_f, convw, convb,
                           bn0g, bn0b, bn1g, bn1b, phfhi, phflo);

    dim3 gFCF(3, NEDGE / 128);
    dim3 gFCN(1, NEDGE / 128);
    gemm_fc<0><<<gFCF, 256, GEMM_SMEM>>>(phfhi, phflo, FLATSZ, pfchi, pfclo,
                                         FLATSZ, FLATSZ / 64, ph2, DDIM, NEDGE, DDIM,
                                         fcb, bn2g, bn2b);
    gemm_fc<1><<<gFCN, 256, GEMM_SMEM>>>(phfhi, phflo, FLATSZ, pfchi, pfclo,
                                         FLATSZ, FLATSZ / 64, ph2, DDIM, NEDGE, DDIM,
                                         fcb, bn2g, bn2b);

    k_fc1<<<(NEDGE * NCLASS + 255) / 256, 256>>>(ph2, fc1w, fc1b, out);
}

// round 16
// speedup vs baseline: 1.5440x; 1.1048x over previous
#include <cuda_runtime.h>
#include <cuda_bf16.h>
#include <cstdint>

typedef __nv_bfloat16 bf16;
typedef unsigned long long u64;

// ---------------- problem constants ----------------
#define NNODES 5000
#define NEDGE  8192
#define DDIM   200
#define NLAYER 6
#define NFILT  96
#define FLATSZ 18816      // 96*14*14 = 294*64
#define NCLASS 13

#define MPADX   5120
#define KPAD    256
#define E2      (2*NEDGE)

// ---------------- device scratch (static, no allocs) ----------------
__device__ __align__(256) float g_x[NNODES * DDIM];
__device__ __align__(256) bf16  g_xhi[MPADX * KPAD], g_xlo[MPADX * KPAD];
__device__ __align__(256) bf16  g_relhi[2][E2 * KPAD], g_rello[2][E2 * KPAD];
__device__ __align__(256) bf16  g_thi[E2 * KPAD], g_tlo[E2 * KPAD];
__device__ __align__(256) float g_agg[NNODES * DDIM];
__device__ __align__(256) float g_deg[2 * NNODES];
__device__ __align__(256) float g_scale[2 * NEDGE];
__device__ __align__(256) bf16  g_hfhi[(size_t)NEDGE * FLATSZ], g_hflo[(size_t)NEDGE * FLATSZ];
__device__ __align__(256) float g_h2[NEDGE * DDIM];
__device__ __align__(256) bf16  g_wthi[24 * KPAD * KPAD], g_wtlo[24 * KPAD * KPAD];
__device__ __align__(256) bf16  g_fchi[256 * FLATSZ], g_fclo[256 * FLATSZ];

// ---------------- fp32x2 / bf16 helpers ----------------
__device__ __forceinline__ void fma2(u64& d, u64 a, u64 b) {
    asm("fma.rn.f32x2 %0, %1, %2, %0;" : "+l"(d) : "l"(a), "l"(b));
}
__device__ __forceinline__ float2 unpk(u64 v) {
    float2 r; asm("mov.b64 {%0, %1}, %2;" : "=f"(r.x), "=f"(r.y) : "l"(v)); return r;
}
__device__ __forceinline__ u64 pk2(float a, float b) {
    u64 r; asm("mov.b64 %0, {%1, %2};" : "=l"(r) : "f"(a), "f"(b)); return r;
}
__device__ __forceinline__ void split2(float v, bf16& h, bf16& l) {
    h = __float2bfloat16(v);
    l = __float2bfloat16(v - __bfloat162float(h));
}

// ---------------- mma.sync / ldmatrix / cp.async helpers ----------------
__device__ __forceinline__ uint32_t smem_u32(const void* p) {
    uint32_t a;
    asm("{ .reg .u64 t; cvta.to.shared.u64 t, %1; cvt.u32.u64 %0, t; }" : "=r"(a) : "l"(p));
    return a;
}
__device__ __forceinline__ void ldm4(uint32_t addr, uint32_t* r) {
    asm volatile("ldmatrix.sync.aligned.m8n8.x4.shared.b16 {%0,%1,%2,%3}, [%4];"
                 : "=r"(r[0]), "=r"(r[1]), "=r"(r[2]), "=r"(r[3]) : "r"(addr));
}
__device__ __forceinline__ void mma16816(float* c, const uint32_t* a,
                                         uint32_t b0, uint32_t b1) {
    asm volatile(
        "mma.sync.aligned.m16n8k16.row.col.f32.bf16.bf16.f32 "
        "{%0,%1,%2,%3}, {%4,%5,%6,%7}, {%8,%9}, {%0,%1,%2,%3};"
        : "+f"(c[0]), "+f"(c[1]), "+f"(c[2]), "+f"(c[3])
        : "r"(a[0]), "r"(a[1]), "r"(a[2]), "r"(a[3]), "r"(b0), "r"(b1));
}
#define CPA16(dst, src) \
    asm volatile("cp.async.cg.shared.global [%0], [%1], 16;" :: "r"(dst), "l"(src) : "memory")
#define CPA_COMMIT() asm volatile("cp.async.commit_group;" ::: "memory")

// ------- GEMM core: CTA tile 128x64, K-chunk 64, 8 warps (4m x 2n), 2 CTAs/SM -------
#define STGBYTES 55296
#define ALO_OFF  18432
#define BHI_OFF  36864
#define BLO_OFF  46080

struct GemmJob {
    const bf16 *Ahi, *Alo; int lda;
    const bf16 *Bhi, *Blo, *Bhi2, *Blo2; int mswitch;
    int ldb, kiters, mtiles;
    float* C; int ldc;
    int M, N;
    bf16 *Chi, *Clo; int ldcbf;
    const int *eidx, *ieidx;
    const float* sc;
    int epi;  // 0 plain | 2 bf16 split | 3 atomic scatter scaled | 4 atomicAdd
};

#define DEF_LOAD_CHUNK(gAhi_, gAlo_, lda_, gBhi_, gBlo_, ldb_)                             \
    auto load_chunk = [&](int kc, int s) {                                                  \
        const uint32_t sb = smb + s * STGBYTES;                                             \
        const size_t koff = (size_t)kc * 64;                                                \
        _Pragma("unroll") for (int jv = 0; jv < 4; jv++) {                                  \
            const int id = tid + jv * 256;                                                  \
            const int r = id >> 3, c = id & 7;                                              \
            const uint32_t off = (uint32_t)(r * 144 + c * 16);                              \
            const size_t src = (size_t)r * (lda_) + koff + c * 8;                           \
            CPA16(sb + off,           (gAhi_) + src);                                       \
            CPA16(sb + ALO_OFF + off, (gAlo_) + src);                                       \
        }                                                                                   \
        _Pragma("unroll") for (int jv = 0; jv < 2; jv++) {                                  \
            const int id = tid + jv * 256;                                                  \
            const int r = id >> 3, c = id & 7;                                              \
            const uint32_t off = (uint32_t)(r * 144 + c * 16);                              \
            const size_t src = (size_t)r * (ldb_) + koff + c * 8;                           \
            CPA16(sb + BHI_OFF + off, (gBhi_) + src);                                       \
            CPA16(sb + BLO_OFF + off, (gBlo_) + src);                                      \
        }                                                                                   \
        CPA_COMMIT();                                                                       \
    };

// full 128x64 tile mainloop. Per-accumulator product order per ks is hh, lh, hl
// (unchanged from the validated kernel -> bit-identical results), but dependent
// mma on the same accumulator are now separated by 4 independent mma in program
// order (volatile asm preserves this into SASS), hiding HMMA RAW latency.
#define GEMM_CORE(kiters_)                                                                 \
    float acc[2][4][4];                                                                     \
    _Pragma("unroll") for (int mb = 0; mb < 2; mb++)                                        \
    _Pragma("unroll") for (int nb = 0; nb < 4; nb++)                                        \
    _Pragma("unroll") for (int v = 0; v < 4; v++) acc[mb][nb][v] = 0.f;                     \
    const uint32_t aRow = (uint32_t)((wm * 32 + (lane & 15)) * 144 + (lane >> 4) * 16);     \
    const int bg = lane >> 3;                                                               \
    const uint32_t bRow = (uint32_t)((wn * 32 + ((bg >> 1) * 8) + (lane & 7)) * 144         \
                                     + (bg & 1) * 16);                                      \
    load_chunk(0, 0);                                                                       \
    load_chunk(1, 1);                                                                       \
    for (int i = 0; i < (kiters_); i++) {                                                   \
        const int s = i & 1;                                                                \
        if (i + 1 < (kiters_)) asm volatile("cp.async.wait_group 1;" ::: "memory");         \
        else                   asm volatile("cp.async.wait_group 0;" ::: "memory");         \
        __syncthreads();                                                                    \
        const uint32_t sb = smb + s * STGBYTES;                                             \
        _Pragma("unroll") for (int ks = 0; ks < 4; ks++) {                                  \
            uint32_t ah[2][4], al[2][4];                                                    \
            _Pragma("unroll") for (int mb = 0; mb < 2; mb++) {                              \
                const uint32_t a = sb + aRow + (uint32_t)(mb * 16 * 144 + ks * 32);         \
                ldm4(a, ah[mb]);                                                            \
                ldm4(a + ALO_OFF, al[mb]);                                                  \
            }                                                                               \
            _Pragma("unroll") for (int p = 0; p < 2; p++) {                                 \
                uint32_t bh[4], bl[4];                                                      \
                const uint32_t b = sb + BHI_OFF + bRow + (uint32_t)(p * 16 * 144 + ks * 32);\
                ldm4(b, bh);                                                                \
                ldm4(b + (BLO_OFF - BHI_OFF), bl);                                          \
                /* hh for all 4 tiles of this p */                                          \
                _Pragma("unroll") for (int mb = 0; mb < 2; mb++)                            \
                _Pragma("unroll") for (int half = 0; half < 2; half++) {                    \
                    const int o = half * 2;                                                 \
                    mma16816(acc[mb][p * 2 + half], ah[mb], bh[o], bh[o + 1]);              \
                }                                                                           \
                /* lh for all 4 tiles */                                                    \
                _Pragma("unroll") for (int mb = 0; mb < 2; mb++)                            \
                _Pragma("unroll") for (int half = 0; half < 2; half++) {                    \
                    const int o = half * 2;                                                 \
                    mma16816(acc[mb][p * 2 + half], al[mb], bh[o], bh[o + 1]);              \
                }                                                                           \
                /* hl for all 4 tiles */                                                    \
                _Pragma("unroll") for (int mb = 0; mb < 2; mb++)                            \
                _Pragma("unroll") for (int half = 0; half < 2; half++) {                    \
                    const int o = half * 2;                                                 \
                    mma16816(acc[mb][p * 2 + half], ah[mb], bl[o], bl[o + 1]);              \
                }                                                                           \
            }                                                                               \
        }                                                                                   \
        __syncthreads();                                                                    \
        if (i + 2 < (kiters_)) load_chunk(i + 2, s);                                        \
    }

// ---------------- merged per-layer GEMM (msg / loop / rel via blockIdx.z) ----------------
__global__ void __launch_bounds__(256, 2)
gemm_multi(GemmJob j0, GemmJob j1, GemmJob j2) {
    const GemmJob jb = (blockIdx.z == 0) ? j0 : (blockIdx.z == 1) ? j1 : j2;
    if ((int)blockIdx.y >= jb.mtiles) return;

    extern __shared__ __align__(16) char smraw[];
    const int tid  = threadIdx.x;
    const int lane = tid & 31;
    const int wid  = tid >> 5;
    const int wm   = wid >> 1;
    const int wn   = wid & 1;
    const int m0   = blockIdx.y * 128;
    const int n0   = blockIdx.x * 64;

    const bf16* Bh = (m0 >= jb.mswitch) ? jb.Bhi2 : jb.Bhi;
    const bf16* Bl = (m0 >= jb.mswitch) ? jb.Blo2 : jb.Blo;
    const uint32_t smb = smem_u32(smraw);
    const int lda = jb.lda, ldb = jb.ldb, kiters = jb.kiters;
    const bf16* gAhi = jb.Ahi + (size_t)m0 * lda;
    const bf16* gAlo = jb.Alo + (size_t)m0 * lda;
    const bf16* gBhi = Bh + (size_t)n0 * ldb;
    const bf16* gBlo = Bl + (size_t)n0 * ldb;

    DEF_LOAD_CHUNK(gAhi, gAlo, lda, gBhi, gBlo, ldb)

    GEMM_CORE(kiters)

#pragma unroll
    for (int mb = 0; mb < 2; mb++) {
#pragma unroll
        for (int half = 0; half < 2; half++) {
            const int row = m0 + wm * 32 + mb * 16 + (lane >> 2) + half * 8;
            if (row >= jb.M) continue;
            int dst = row;
            float rs = 1.f;
            if (jb.epi == 3) {
                dst = (row < NEDGE) ? jb.eidx[NEDGE + row] : jb.ieidx[row];
                rs = jb.sc[row];
            }
#pragma unroll
            for (int nb = 0; nb < 4; nb++) {
#pragma unroll
                for (int jj = 0; jj < 2; jj++) {
                    const int col = n0 + wn * 32 + nb * 8 + (lane & 3) * 2 + jj;
                    const float v = acc[mb][nb][half * 2 + jj];
                    if (jb.epi == 0) {
                        if (col < jb.N) jb.C[(size_t)row * jb.ldc + col] = v;
                    } else if (jb.epi == 2) {
                        const float vv = (col < jb.N) ? v : 0.f;
                        bf16 h, l; split2(vv, h, l);
                        jb.Chi[(size_t)row * jb.ldcbf + col] = h;
                        jb.Clo[(size_t)row * jb.ldcbf + col] = l;
                    } else if (jb.epi == 3) {
                        if (col < jb.N)
                            atomicAdd(&jb.C[(size_t)dst * jb.ldc + col], v * rs);
                    } else {
                        if (col < jb.N)
                            atomicAdd(&jb.C[(size_t)row * jb.ldc + col], v);
                    }
                }
            }
        }
    }
}

// ---------------- FC GEMM (bias + bn2 + relu fused), bf16x3 ----------------
__global__ void __launch_bounds__(256, 2)
gemm_fc(const bf16* __restrict__ Ahi, const bf16* __restrict__ Alo, int lda,
        const bf16* __restrict__ Bhi, const bf16* __restrict__ Blo, int ldb, int kiters,
        float* __restrict__ C, int ldc, int M, int N,
        const float* __restrict__ bias, const float* __restrict__ g2,
        const float* __restrict__ b2) {
    extern __shared__ __align__(16) char smraw[];
    const int tid  = threadIdx.x;
    const int lane = tid & 31;
    const int wid  = tid >> 5;
    const int wm   = wid >> 1;
    const int wn   = wid & 1;
    const int m0   = blockIdx.y * 128;
    const int n0   = blockIdx.x * 64;

    const uint32_t smb = smem_u32(smraw);
    const bf16* gAhi = Ahi + (size_t)m0 * lda;
    const bf16* gAlo = Alo + (size_t)m0 * lda;
    const bf16* gBhi = Bhi + (size_t)n0 * ldb;
    const bf16* gBlo = Blo + (size_t)n0 * ldb;

    DEF_LOAD_CHUNK(gAhi, gAlo, lda, gBhi, gBlo, ldb)

    GEMM_CORE(kiters)

    const float invs = rsqrtf(1.0f + 1e-5f);
#pragma unroll
    for (int mb = 0; mb < 2; mb++) {
#pragma unroll
        for (int half = 0; half < 2; half++) {
            const int row = m0 + wm * 32 + mb * 16 + (lane >> 2) + half * 8;
            if (row >= M) continue;
#pragma unroll
            for (int nb = 0; nb < 4; nb++) {
#pragma unroll
                for (int jj = 0; jj < 2; jj++) {
                    const int col = n0 + wn * 32 + nb * 8 + (lane & 3) * 2 + jj;
                    if (col < N) {
                        float v = acc[mb][nb][half * 2 + jj];
                        v = (v + bias[col]) * (g2[col] * invs) + b2[col];
                        C[(size_t)row * ldc + col] = fmaxf(v, 0.f);
                    }
                }
            }
        }
    }
}

// ---------------- glue kernels ----------------
__global__ void k_init(const float* __restrict__ nodef, const float* __restrict__ ef,
                       const float* __restrict__ ief,
                       float* __restrict__ x, bf16* __restrict__ xhi, bf16* __restrict__ xlo,
                       bf16* __restrict__ rhi, bf16* __restrict__ rlo,
                       bf16* __restrict__ thi, bf16* __restrict__ tlo,
                       float* __restrict__ agg, float* __restrict__ deg) {
    int idx = blockIdx.x * blockDim.x + threadIdx.x;
    if (idx >= E2 * KPAD) return;
    int row = idx >> 8, d = idx & 255;
    float rv = 0.f;
    if (d < DDIM)
        rv = (row < NEDGE) ? ef[row * DDIM + d] : ief[(row - NEDGE) * DDIM + d];
    bf16 h, l; split2(rv, h, l);
    rhi[idx] = h; rlo[idx] = l;
    if (d >= DDIM) {
        thi[idx] = __float2bfloat16(0.f);
        tlo[idx] = __float2bfloat16(0.f);
    }
    if (row < MPADX) {
        float xv = (row < NNODES && d < DDIM) ? nodef[row * DDIM + d] : 0.f;
        split2(xv, h, l);
        xhi[idx] = h; xlo[idx] = l;
    }
    if (idx < NNODES * DDIM) { x[idx] = nodef[idx]; agg[idx] = 0.f; }
    if (idx < 2 * NNODES) deg[idx] = 0.f;
}

__global__ void k_deg(const int* __restrict__ ei, const int* __restrict__ iei,
                      float* __restrict__ deg) {
    int e = blockIdx.x * blockDim.x + threadIdx.x;
    if (e < NEDGE) {
        atomicAdd(&deg[ei[e]], 1.f);
        atomicAdd(&deg[NNODES + iei[e]], 1.f);
    }
}

__device__ __forceinline__ float dinvf(float v) { return v > 0.f ? rsqrtf(v) : 0.f; }

__global__ void k_norm(const int* __restrict__ ei, const int* __restrict__ iei,
                       const float* __restrict__ deg, float* __restrict__ sc) {
    int e = blockIdx.x * blockDim.x + threadIdx.x;
    if (e < NEDGE) {
        sc[e]         = dinvf(deg[ei[e]]) * dinvf(deg[ei[NEDGE + e]]);
        sc[NEDGE + e] = dinvf(deg[NNODES + iei[e]]) * dinvf(deg[NNODES + iei[NEDGE + e]]);
    }
}

// t = x[src] - rel, 2 elements per thread
__global__ void k_compose(const int* __restrict__ ei, const int* __restrict__ iei,
                          const float* __restrict__ x,
                          const bf16* __restrict__ rhi, const bf16* __restrict__ rlo,
                          bf16* __restrict__ thi, bf16* __restrict__ tlo) {
    int idx = blockIdx.x * blockDim.x + threadIdx.x;
    if (idx >= E2 * (DDIM / 2)) return;
    int row = idx / (DDIM / 2);
    int dp = (idx - row * (DDIM / 2)) * 2;
    int src = (row < NEDGE) ? ei[row] : iei[row - NEDGE];
    const float2 xv = *(const float2*)&x[src * DDIM + dp];
    const int ridx = row * KPAD + dp;
    const __nv_bfloat162 rh = *(const __nv_bfloat162*)&rhi[ridx];
    const __nv_bfloat162 rl = *(const __nv_bfloat162*)&rlo[ridx];
    float v0 = xv.x - (__bfloat162float(rh.x) + __bfloat162float(rl.x));
    float v1 = xv.y - (__bfloat162float(rh.y) + __bfloat162float(rl.y));
    bf16 h0, l0, h1, l1;
    split2(v0, h0, l0);
    split2(v1, h1, l1);
    *(__nv_bfloat162*)&thi[ridx] = __nv_bfloat162(h0, h1);
    *(__nv_bfloat162*)&tlo[ridx] = __nv_bfloat162(l0, l1);
}

// tanh activation, 2 elems/thread; re-zeroes agg
__global__ void k_act(const float* __restrict__ aggc, float* __restrict__ aggz,
                      const float* __restrict__ b, float* __restrict__ x,
                      bf16* __restrict__ xhi, bf16* __restrict__ xlo) {
    int idx = blockIdx.x * blockDim.x + threadIdx.x;
    if (idx >= NNODES * (DDIM / 2)) return;
    int row = idx / (DDIM / 2);
    int dp = (idx - row * (DDIM / 2)) * 2;
    const int gi = row * DDIM + dp;
    const float2 a = *(const float2*)&aggc[gi];
    *(float2*)&aggz[gi] = make_float2(0.f, 0.f);
    float v0 = tanhf(a.x * (1.0f / 3.0f) + b[dp]);
    float v1 = tanhf(a.y * (1.0f / 3.0f) + b[dp + 1]);
    *(float2*)&x[gi] = make_float2(v0, v1);
    bf16 h0, l0, h1, l1;
    split2(v0, h0, l0);
    split2(v1, h1, l1);
    const int ridx = row * KPAD + dp;
    *(__nv_bfloat162*)&xhi[ridx] = __nv_bfloat162(h0, h1);
    *(__nv_bfloat162*)&xlo[ridx] = __nv_bfloat162(l0, l1);
}

// weight prep: 24 matrices [200,200] -> transposed bf16 hi/lo [256,256]
__global__ void k_prep_wt(const float* __restrict__ Win, const float* __restrict__ Wout,
                          const float* __restrict__ Wloop, const float* __restrict__ Wrel,
                          bf16* __restrict__ hi, bf16* __restrict__ lo) {
    int idx = blockIdx.x * blockDim.x + threadIdx.x;
    if (idx >= 24 * KPAD * KPAD) return;
    int m = idx >> 16;
    int n = (idx >> 8) & 255;
    int k = idx & 255;
    float v = 0.f;
    if (n < DDIM && k < DDIM) {
        int t = m / 6, l = m % 6;
        const float* s = (t == 0) ? Win : (t == 1) ? Wout : (t == 2) ? Wloop : Wrel;
        v = s[l * DDIM * DDIM + k * DDIM + n];
    }
    bf16 h, l2; split2(v, h, l2);
    hi[idx] = h; lo[idx] = l2;
}

// fc_w [200, FLATSZ] -> bf16 hi/lo [256, FLATSZ] (rows >= 200 zero)
__global__ void k_prep_fc(const float* __restrict__ fcw,
                          bf16* __restrict__ hi, bf16* __restrict__ lo) {
    size_t idx = (size_t)blockIdx.x * blockDim.x + threadIdx.x;
    if (idx >= (size_t)256 * FLATSZ) return;
    int r = (int)(idx / FLATSZ);
    float v = (r < DDIM) ? fcw[idx] : 0.f;
    bf16 h, l; split2(v, h, l);
    hi[idx] = h; lo[idx] = l;
}

// ---------------- ConvE conv, FFMA2 filter-pair version ----------------
__global__ void __launch_bounds__(224, 2)
k_conv(const int* __restrict__ ei, const float* __restrict__ x,
       const bf16* __restrict__ rhi, const bf16* __restrict__ rlo,
       const float* __restrict__ conv_w, const float* __restrict__ conv_b,
       const float* __restrict__ bn0g, const float* __restrict__ bn0b,
       const float* __restrict__ bn1g, const float* __restrict__ bn1b,
       bf16* __restrict__ hfhi, bf16* __restrict__ hflo) {
    __shared__ __align__(16) u64 wp[48][50];
    __shared__ float img[400];
    __shared__ float cb[NFILT], s1[NFILT], b1[NFILT];

    const int e = blockIdx.x;
    const int tid = threadIdx.x;
    const float invs = rsqrtf(1.0f + 1e-5f);

    for (int i = tid; i < 48 * 50; i += 224) {
        int f2 = i / 50, t = i - f2 * 50;
        wp[f2][t] = (t < 49) ? pk2(conv_w[(2 * f2) * 49 + t], conv_w[(2 * f2 + 1) * 49 + t])
                             : 0ULL;
    }
    for (int i = tid; i < NFILT; i += 224) {
        cb[i] = conv_b[i];
        s1[i] = bn1g[i] * invs;
        b1[i] = bn1b[i];
    }
    const float sc0 = bn0g[0] * invs;
    const float bb0 = bn0b[0];
    const int sub = ei[e];
    for (int i = tid; i < 400; i += 224) {
        int ii = i / 20, jj = i - ii * 20;
        int k = ii * 10 + (jj >> 1);
        float v;
        if (jj & 1)
            v = __bfloat162float(rhi[e * KPAD + k]) + __bfloat162float(rlo[e * KPAD + k]);
        else
            v = x[sub * DDIM + k];
        img[i] = v * sc0 + bb0;
    }
    __syncthreads();

    if (tid < 196) {
        const int oi = tid / 14, oj = tid - oi * 14;
        u64 pd[50];
#pragma unroll
        for (int a = 0; a < 7; a++)
#pragma unroll
            for (int b = 0; b < 7; b++) {
                float p = img[(oi + a) * 20 + oj + b];
                pd[a * 7 + b] = pk2(p, p);
            }
        pd[49] = 0ULL;

        const size_t obase = (size_t)e * FLATSZ + tid;
        for (int f2 = 0; f2 < 48; f2++) {
            u64 acc = 0ULL;
#pragma unroll
            for (int t2 = 0; t2 < 25; t2++) {
                ulonglong2 w2 = *(const ulonglong2*)&wp[f2][2 * t2];
                fma2(acc, pd[2 * t2], w2.x);
                fma2(acc, pd[2 * t2 + 1], w2.y);
            }
            float2 vv = unpk(acc);
            const int f0 = 2 * f2, f1 = 2 * f2 + 1;
            float v0 = fmaxf((vv.x + cb[f0]) * s1[f0] + b1[f0], 0.f);
            float v1 = fmaxf((vv.y + cb[f1]) * s1[f1] + b1[f1], 0.f);
            bf16 h, l;
            split2(v0, h, l);
            hfhi[obase + (size_t)f0 * 196] = h; hflo[obase + (size_t)f0 * 196] = l;
            split2(v1, h, l);
            hfhi[obase + (size_t)f1 * 196] = h; hflo[obase + (size_t)f1 * 196] = l;
        }
    }
}

// ---------------- final tiny FC ----------------
__global__ void k_fc1(const float* __restrict__ h2, const float* __restrict__ fc1w,
                      const float* __restrict__ fc1b, float* __restrict__ out) {
    int idx = blockIdx.x * blockDim.x + threadIdx.x;
    if (idx < NEDGE * NCLASS) {
        int e = idx / NCLASS, c = idx - e * NCLASS;
        const float* h = h2 + e * DDIM;
        const float* w = fc1w + c * DDIM;
        float s = fc1b[c];
#pragma unroll 4
        for (int k = 0; k < DDIM; k++) s += h[k] * w[k];
        out[idx] = s;
    }
}

// ---------------- host launcher ----------------
extern "C" void kernel_launch(void* const* d_in, const int* in_sizes, int n_in,
                              void* d_out, int out_size) {
    const float* nodef = (const float*)d_in[0];
    const float* ef    = (const float*)d_in[1];
    const float* ief   = (const float*)d_in[2];
    const float* Win   = (const float*)d_in[3];
    const float* Wout  = (const float*)d_in[4];
    const float* Wloop = (const float*)d_in[5];
    const float* Wrel  = (const float*)d_in[6];
    const float* bgcn  = (const float*)d_in[7];
    const float* bn0g  = (const float*)d_in[8];
    const float* bn0b  = (const float*)d_in[9];
    const float* convw = (const float*)d_in[10];
    const float* convb = (const float*)d_in[11];
    const float* bn1g  = (const float*)d_in[12];
    const float* bn1b  = (const float*)d_in[13];
    const float* fcw   = (const float*)d_in[14];
    const float* fcb   = (const float*)d_in[15];
    const float* bn2g  = (const float*)d_in[16];
    const float* bn2b  = (const float*)d_in[17];
    const float* fc1w  = (const float*)d_in[18];
    const float* fc1b  = (const float*)d_in[19];
    const int*   ei    = (const int*)d_in[20];
    const int*   iei   = (const int*)d_in[21];
    float* out = (float*)d_out;

    float *px, *pagg, *pdeg, *psc, *ph2;
    bf16 *pxhi, *pxlo, *prhi0, *prlo0, *pthi, *ptlo, *phfhi, *phflo, *pwthi, *pwtlo, *pfchi, *pfclo;
    cudaGetSymbolAddress((void**)&px,    g_x);
    cudaGetSymbolAddress((void**)&pxhi,  g_xhi);
    cudaGetSymbolAddress((void**)&pxlo,  g_xlo);
    cudaGetSymbolAddress((void**)&prhi0, g_relhi);
    cudaGetSymbolAddress((void**)&prlo0, g_rello);
    cudaGetSymbolAddress((void**)&pthi,  g_thi);
    cudaGetSymbolAddress((void**)&ptlo,  g_tlo);
    cudaGetSymbolAddress((void**)&pagg,  g_agg);
    cudaGetSymbolAddress((void**)&pdeg,  g_deg);
    cudaGetSymbolAddress((void**)&psc,   g_scale);
    cudaGetSymbolAddress((void**)&phfhi, g_hfhi);
    cudaGetSymbolAddress((void**)&phflo, g_hflo);
    cudaGetSymbolAddress((void**)&ph2,   g_h2);
    cudaGetSymbolAddress((void**)&pwthi, g_wthi);
    cudaGetSymbolAddress((void**)&pwtlo, g_wtlo);
    cudaGetSymbolAddress((void**)&pfchi, g_fchi);
    cudaGetSymbolAddress((void**)&pfclo, g_fclo);

    const int GEMM_SMEM = 2 * STGBYTES;
    cudaFuncSetAttribute(gemm_multi, cudaFuncAttributeMaxDynamicSharedMemorySize, GEMM_SMEM);
    cudaFuncSetAttribute(gemm_fc,    cudaFuncAttributeMaxDynamicSharedMemorySize, GEMM_SMEM);

    const int RELSZ = E2 * KPAD;
    const int WMAT = KPAD * KPAD;
    const int NONE_SW = 0x40000000;

    auto make_jobs = [&](int l, int cur, GemmJob& j0, GemmJob& j1, GemmJob& j2) {
        bf16* rhi_c = prhi0 + cur * RELSZ;
        bf16* rlo_c = prlo0 + cur * RELSZ;
        bf16* rhi_n = prhi0 + (1 - cur) * RELSZ;
        bf16* rlo_n = prlo0 + (1 - cur) * RELSZ;
        j0 = { pthi, ptlo, KPAD,
               pwthi + (0 * 6 + l) * WMAT, pwtlo + (0 * 6 + l) * WMAT,
               pwthi + (1 * 6 + l) * WMAT, pwtlo + (1 * 6 + l) * WMAT, NEDGE,
               KPAD, KPAD / 64, E2 / 128,
               pagg, DDIM, E2, DDIM, nullptr, nullptr, 0, ei, iei, psc, 3 };
        j1 = { pxhi, pxlo, KPAD,
               pwthi + (2 * 6 + l) * WMAT, pwtlo + (2 * 6 + l) * WMAT,
               pwthi + (2 * 6 + l) * WMAT, pwtlo + (2 * 6 + l) * WMAT, NONE_SW,
               KPAD, KPAD / 64, MPADX / 128,
               pagg, DDIM, NNODES, DDIM, nullptr, nullptr, 0,
               nullptr, nullptr, nullptr, 4 };
        j2 = { rhi_c, rlo_c, KPAD,
               pwthi + (3 * 6 + l) * WMAT, pwtlo + (3 * 6 + l) * WMAT,
               pwthi + (3 * 6 + l) * WMAT, pwtlo + (3 * 6 + l) * WMAT, NONE_SW,
               KPAD, KPAD / 64, E2 / 128,
               nullptr, 0, E2, DDIM, rhi_n, rlo_n, KPAD,
               nullptr, nullptr, nullptr, 2 };
    };

    k_init<<<(E2 * KPAD + 255) / 256, 256>>>(nodef, ef, ief, px, pxhi, pxlo,
                                             prhi0, prlo0, pthi, ptlo, pagg, pdeg);
    k_prep_wt<<<(24 * WMAT + 255) / 256, 256>>>(Win, Wout, Wloop, Wrel, pwthi, pwtlo);
    k_deg<<<(NEDGE + 255) / 256, 256>>>(ei, iei, pdeg);
    k_compose<<<(E2 * (DDIM / 2) + 255) / 256, 256>>>(ei, iei, px, prhi0, prlo0,
                                                      pthi, ptlo);
    k_norm<<<(NEDGE + 255) / 256, 256>>>(ei, iei, pdeg, psc);
    k_prep_fc<<<(int)(((size_t)256 * FLATSZ + 255) / 256), 256>>>(fcw, pfchi, pfclo);

    dim3 gMulti(4, 128, 3);
    int cur = 0;
    for (int l = 0; l < NLAYER; l++) {
        if (l > 0) {
            bf16* rhi_c = prhi0 + cur * RELSZ;
            bf16* rlo_c = prlo0 + cur * RELSZ;
            k_compose<<<(E2 * (DDIM / 2) + 255) / 256, 256>>>(ei, iei, px, rhi_c, rlo_c,
                                                              pthi, ptlo);
        }
        GemmJob j0, j1, j2;
        make_jobs(l, cur, j0, j1, j2);
        gemm_multi<<<gMulti, 256, GEMM_SMEM>>>(j0, j1, j2);
        k_act<<<(NNODES * (DDIM / 2) + 255) / 256, 256>>>(pagg, pagg, bgcn + l * DDIM,
                                                          px, pxhi, pxlo);
        cur ^= 1;
    }
    bf16* rhi_f = prhi0 + cur * RELSZ;
    bf16* rlo_f = prlo0 + cur * RELSZ;

    k_conv<<<NEDGE, 224>>>(ei, px, rhi_f, rlo_f, convw, convb,
                           bn0g, bn0b, bn1g, bn1b, phfhi, phflo);

    dim3 gFC(4, NEDGE / 128);
    gemm_fc<<<gFC, 256, GEMM_SMEM>>>(phfhi, phflo, FLATSZ, pfchi, pfclo,
                                     FLATSZ, FLATSZ / 64, ph2, DDIM, NEDGE, DDIM,
                                     fcb, bn2g, bn2b);

    k_fc1<<<(NEDGE * NCLASS + 255) / 256, 256>>>(ph2, fc1w, fc1b, out);
}

// round 17
// speedup vs baseline: 1.7412x; 1.1277x over previous
#include <cuda_runtime.h>
#include <cuda_bf16.h>
#include <cuda_fp16.h>
#include <cstdint>

typedef __nv_bfloat16 bf16;
typedef __half f16;
typedef unsigned long long u64;

// ---------------- problem constants ----------------
#define NNODES 5000
#define NEDGE  8192
#define DDIM   200
#define NLAYER 6
#define NFILT  96
#define FLATSZ 18816      // 96*14*14 = 294*64
#define NCLASS 13

#define MPADX   5120
#define KPAD    256
#define E2      (2*NEDGE)

// ---------------- device scratch (static, no allocs) ----------------
__device__ __align__(256) float g_x[NNODES * DDIM];
__device__ __align__(256) bf16  g_xhi[MPADX * KPAD], g_xlo[MPADX * KPAD];
__device__ __align__(256) bf16  g_relhi[2][E2 * KPAD], g_rello[2][E2 * KPAD];
__device__ __align__(256) bf16  g_thi[E2 * KPAD], g_tlo[E2 * KPAD];
__device__ __align__(256) float g_agg[NNODES * DDIM];
__device__ __align__(256) float g_deg[2 * NNODES];
__device__ __align__(256) float g_scale[2 * NEDGE];
__device__ __align__(256) f16   g_hfhi[(size_t)NEDGE * FLATSZ], g_hflo[(size_t)NEDGE * FLATSZ];
__device__ __align__(256) float g_h2[NEDGE * DDIM];
__device__ __align__(256) bf16  g_wthi[24 * KPAD * KPAD], g_wtlo[24 * KPAD * KPAD];
__device__ __align__(256) f16   g_fch[(size_t)256 * FLATSZ];   // fc_w in fp16 (single)

// ---------------- fp32x2 / bf16 / fp16 helpers ----------------
__device__ __forceinline__ void fma2(u64& d, u64 a, u64 b) {
    asm("fma.rn.f32x2 %0, %1, %2, %0;" : "+l"(d) : "l"(a), "l"(b));
}
__device__ __forceinline__ float2 unpk(u64 v) {
    float2 r; asm("mov.b64 {%0, %1}, %2;" : "=f"(r.x), "=f"(r.y) : "l"(v)); return r;
}
__device__ __forceinline__ u64 pk2(float a, float b) {
    u64 r; asm("mov.b64 %0, {%1, %2};" : "=l"(r) : "f"(a), "f"(b)); return r;
}
__device__ __forceinline__ void split2(float v, bf16& h, bf16& l) {
    h = __float2bfloat16(v);
    l = __float2bfloat16(v - __bfloat162float(h));
}
__device__ __forceinline__ void split2h(float v, f16& h, f16& l) {
    h = __float2half(v);
    l = __float2half(v - __half2float(h));
}

// ---------------- mma.sync / ldmatrix / cp.async helpers ----------------
__device__ __forceinline__ uint32_t smem_u32(const void* p) {
    uint32_t a;
    asm("{ .reg .u64 t; cvta.to.shared.u64 t, %1; cvt.u32.u64 %0, t; }" : "=r"(a) : "l"(p));
    return a;
}
__device__ __forceinline__ void ldm4(uint32_t addr, uint32_t* r) {
    asm volatile("ldmatrix.sync.aligned.m8n8.x4.shared.b16 {%0,%1,%2,%3}, [%4];"
                 : "=r"(r[0]), "=r"(r[1]), "=r"(r[2]), "=r"(r[3]) : "r"(addr));
}
__device__ __forceinline__ void mma16816(float* c, const uint32_t* a,
                                         uint32_t b0, uint32_t b1) {
    asm volatile(
        "mma.sync.aligned.m16n8k16.row.col.f32.bf16.bf16.f32 "
        "{%0,%1,%2,%3}, {%4,%5,%6,%7}, {%8,%9}, {%0,%1,%2,%3};"
        : "+f"(c[0]), "+f"(c[1]), "+f"(c[2]), "+f"(c[3])
        : "r"(a[0]), "r"(a[1]), "r"(a[2]), "r"(a[3]), "r"(b0), "r"(b1));
}
__device__ __forceinline__ void mma16816h(float* c, const uint32_t* a,
                                          uint32_t b0, uint32_t b1) {
    asm volatile(
        "mma.sync.aligned.m16n8k16.row.col.f32.f16.f16.f32 "
        "{%0,%1,%2,%3}, {%4,%5,%6,%7}, {%8,%9}, {%0,%1,%2,%3};"
        : "+f"(c[0]), "+f"(c[1]), "+f"(c[2]), "+f"(c[3])
        : "r"(a[0]), "r"(a[1]), "r"(a[2]), "r"(a[3]), "r"(b0), "r"(b1));
}
#define CPA16(dst, src) \
    asm volatile("cp.async.cg.shared.global [%0], [%1], 16;" :: "r"(dst), "l"(src) : "memory")
#define CPA_COMMIT() asm volatile("cp.async.commit_group;" ::: "memory")

// ------- bf16x3 GEMM core (GCN): CTA 128x64, K-chunk 64, 8 warps, 2 CTAs/SM -------
#define STGBYTES 55296
#define ALO_OFF  18432
#define BHI_OFF  36864
#define BLO_OFF  46080

struct GemmJob {
    const bf16 *Ahi, *Alo; int lda;
    const bf16 *Bhi, *Blo, *Bhi2, *Blo2; int mswitch;
    int ldb, kiters, mtiles;
    float* C; int ldc;
    int M, N;
    bf16 *Chi, *Clo; int ldcbf;
    const int *eidx, *ieidx;
    const float* sc;
    int epi;  // 0 plain | 2 bf16 split | 3 atomic scatter scaled | 4 atomicAdd
};

#define DEF_LOAD_CHUNK(gAhi_, gAlo_, lda_, gBhi_, gBlo_, ldb_)                             \
    auto load_chunk = [&](int kc, int s) {                                                  \
        const uint32_t sb = smb + s * STGBYTES;                                             \
        const size_t koff = (size_t)kc * 64;                                                \
        _Pragma("unroll") for (int jv = 0; jv < 4; jv++) {                                  \
            const int id = tid + jv * 256;                                                  \
            const int r = id >> 3, c = id & 7;                                              \
            const uint32_t off = (uint32_t)(r * 144 + c * 16);                              \
            const size_t src = (size_t)r * (lda_) + koff + c * 8;                           \
            CPA16(sb + off,           (gAhi_) + src);                                       \
            CPA16(sb + ALO_OFF + off, (gAlo_) + src);                                       \
        }                                                                                   \
        _Pragma("unroll") for (int jv = 0; jv < 2; jv++) {                                  \
            const int id = tid + jv * 256;                                                  \
            const int r = id >> 3, c = id & 7;                                              \
            const uint32_t off = (uint32_t)(r * 144 + c * 16);                              \
            const size_t src = (size_t)r * (ldb_) + koff + c * 8;                           \
            CPA16(sb + BHI_OFF + off, (gBhi_) + src);                                       \
            CPA16(sb + BLO_OFF + off, (gBlo_) + src);                                      \
        }                                                                                   \
        CPA_COMMIT();                                                                       \
    };

#define GEMM_CORE(kiters_)                                                                 \
    float acc[2][4][4];                                                                     \
    _Pragma("unroll") for (int mb = 0; mb < 2; mb++)                                        \
    _Pragma("unroll") for (int nb = 0; nb < 4; nb++)                                        \
    _Pragma("unroll") for (int v = 0; v < 4; v++) acc[mb][nb][v] = 0.f;                     \
    const uint32_t aRow = (uint32_t)((wm * 32 + (lane & 15)) * 144 + (lane >> 4) * 16);     \
    const int bg = lane >> 3;                                                               \
    const uint32_t bRow = (uint32_t)((wn * 32 + ((bg >> 1) * 8) + (lane & 7)) * 144         \
                                     + (bg & 1) * 16);                                      \
    load_chunk(0, 0);                                                                       \
    load_chunk(1, 1);                                                                       \
    for (int i = 0; i < (kiters_); i++) {                                                   \
        const int s = i & 1;                                                                \
        if (i + 1 < (kiters_)) asm volatile("cp.async.wait_group 1;" ::: "memory");         \
        else                   asm volatile("cp.async.wait_group 0;" ::: "memory");         \
        __syncthreads();                                                                    \
        const uint32_t sb = smb + s * STGBYTES;                                             \
        _Pragma("unroll") for (int ks = 0; ks < 4; ks++) {                                  \
            uint32_t ah[2][4], al[2][4];                                                    \
            _Pragma("unroll") for (int mb = 0; mb < 2; mb++) {                              \
                const uint32_t a = sb + aRow + (uint32_t)(mb * 16 * 144 + ks * 32);         \
                ldm4(a, ah[mb]);                                                            \
                ldm4(a + ALO_OFF, al[mb]);                                                  \
            }                                                                               \
            _Pragma("unroll") for (int p = 0; p < 2; p++) {                                 \
                uint32_t bh[4], bl[4];                                                      \
                const uint32_t b = sb + BHI_OFF + bRow + (uint32_t)(p * 16 * 144 + ks * 32);\
                ldm4(b, bh);                                                                \
                ldm4(b + (BLO_OFF - BHI_OFF), bl);                                          \
                _Pragma("unroll") for (int mb = 0; mb < 2; mb++)                            \
                _Pragma("unroll") for (int half = 0; half < 2; half++) {                    \
                    const int o = half * 2;                                                 \
                    mma16816(acc[mb][p * 2 + half], ah[mb], bh[o], bh[o + 1]);              \
                }                                                                           \
                _Pragma("unroll") for (int mb = 0; mb < 2; mb++)                            \
                _Pragma("unroll") for (int half = 0; half < 2; half++) {                    \
                    const int o = half * 2;                                                 \
                    mma16816(acc[mb][p * 2 + half], al[mb], bh[o], bh[o + 1]);              \
                }                                                                           \
                _Pragma("unroll") for (int mb = 0; mb < 2; mb++)                            \
                _Pragma("unroll") for (int half = 0; half < 2; half++) {                    \
                    const int o = half * 2;                                                 \
                    mma16816(acc[mb][p * 2 + half], ah[mb], bl[o], bl[o + 1]);              \
                }                                                                           \
            }                                                                               \
        }                                                                                   \
        __syncthreads();                                                                    \
        if (i + 2 < (kiters_)) load_chunk(i + 2, s);                                        \
    }

// ---------------- merged per-layer GEMM (msg / loop / rel via blockIdx.z) ----------------
__global__ void __launch_bounds__(256, 2)
gemm_multi(GemmJob j0, GemmJob j1, GemmJob j2) {
    const GemmJob jb = (blockIdx.z == 0) ? j0 : (blockIdx.z == 1) ? j1 : j2;
    if ((int)blockIdx.y >= jb.mtiles) return;

    extern __shared__ __align__(16) char smraw[];
    const int tid  = threadIdx.x;
    const int lane = tid & 31;
    const int wid  = tid >> 5;
    const int wm   = wid >> 1;
    const int wn   = wid & 1;
    const int m0   = blockIdx.y * 128;
    const int n0   = blockIdx.x * 64;

    const bf16* Bh = (m0 >= jb.mswitch) ? jb.Bhi2 : jb.Bhi;
    const bf16* Bl = (m0 >= jb.mswitch) ? jb.Blo2 : jb.Blo;
    const uint32_t smb = smem_u32(smraw);
    const int lda = jb.lda, ldb = jb.ldb, kiters = jb.kiters;
    const bf16* gAhi = jb.Ahi + (size_t)m0 * lda;
    const bf16* gAlo = jb.Alo + (size_t)m0 * lda;
    const bf16* gBhi = Bh + (size_t)n0 * ldb;
    const bf16* gBlo = Bl + (size_t)n0 * ldb;

    DEF_LOAD_CHUNK(gAhi, gAlo, lda, gBhi, gBlo, ldb)

    GEMM_CORE(kiters)

#pragma unroll
    for (int mb = 0; mb < 2; mb++) {
#pragma unroll
        for (int half = 0; half < 2; half++) {
            const int row = m0 + wm * 32 + mb * 16 + (lane >> 2) + half * 8;
            if (row >= jb.M) continue;
            int dst = row;
            float rs = 1.f;
            if (jb.epi == 3) {
                dst = (row < NEDGE) ? jb.eidx[NEDGE + row] : jb.ieidx[row];
                rs = jb.sc[row];
            }
#pragma unroll
            for (int nb = 0; nb < 4; nb++) {
#pragma unroll
                for (int jj = 0; jj < 2; jj++) {
                    const int col = n0 + wn * 32 + nb * 8 + (lane & 3) * 2 + jj;
                    const float v = acc[mb][nb][half * 2 + jj];
                    if (jb.epi == 0) {
                        if (col < jb.N) jb.C[(size_t)row * jb.ldc + col] = v;
                    } else if (jb.epi == 2) {
                        const float vv = (col < jb.N) ? v : 0.f;
                        bf16 h, l; split2(vv, h, l);
                        jb.Chi[(size_t)row * jb.ldcbf + col] = h;
                        jb.Clo[(size_t)row * jb.ldcbf + col] = l;
                    } else if (jb.epi == 3) {
                        if (col < jb.N)
                            atomicAdd(&jb.C[(size_t)dst * jb.ldc + col], v * rs);
                    } else {
                        if (col < jb.N)
                            atomicAdd(&jb.C[(size_t)row * jb.ldc + col], v);
                    }
                }
            }
        }
    }
}

// ---------------- FC GEMM: fp16 x2 (A = hi+lo fp16, B = fp16 single) ----------------
// result = (Ahi + Alo) @ Bh^T ; only error source is B's fp16 quantization (2^-12).
// 16 mma / ks instead of 24. Stage = (128+128+64) rows * 144B = 46080.
#define FC_STG  46080
#define FC_ALO  18432
#define FC_B    36864

__global__ void __launch_bounds__(256, 2)
gemm_fc(const f16* __restrict__ Ahi, const f16* __restrict__ Alo, int lda,
        const f16* __restrict__ Bh, int ldb, int kiters,
        float* __restrict__ C, int ldc, int M, int N,
        const float* __restrict__ bias, const float* __restrict__ g2,
        const float* __restrict__ b2) {
    extern __shared__ __align__(16) char smraw[];
    const int tid  = threadIdx.x;
    const int lane = tid & 31;
    const int wid  = tid >> 5;
    const int wm   = wid >> 1;
    const int wn   = wid & 1;
    const int m0   = blockIdx.y * 128;
    const int n0   = blockIdx.x * 64;

    const uint32_t smb = smem_u32(smraw);
    const f16* gAhi = Ahi + (size_t)m0 * lda;
    const f16* gAlo = Alo + (size_t)m0 * lda;
    const f16* gB   = Bh + (size_t)n0 * ldb;

    float acc[2][4][4];
#pragma unroll
    for (int mb = 0; mb < 2; mb++)
#pragma unroll
        for (int nb = 0; nb < 4; nb++)
#pragma unroll
            for (int v = 0; v < 4; v++) acc[mb][nb][v] = 0.f;

    auto load_chunk = [&](int kc, int s) {
        const uint32_t sb = smb + s * FC_STG;
        const size_t koff = (size_t)kc * 64;
#pragma unroll
        for (int jv = 0; jv < 4; jv++) {
            const int id = tid + jv * 256;
            const int r = id >> 3, c = id & 7;
            const uint32_t off = (uint32_t)(r * 144 + c * 16);
            const size_t src = (size_t)r * lda + koff + c * 8;
            CPA16(sb + off,          gAhi + src);
            CPA16(sb + FC_ALO + off, gAlo + src);
        }
#pragma unroll
        for (int jv = 0; jv < 2; jv++) {
            const int id = tid + jv * 256;
            const int r = id >> 3, c = id & 7;
            const uint32_t off = (uint32_t)(r * 144 + c * 16);
            CPA16(sb + FC_B + off, gB + (size_t)r * ldb + koff + c * 8);
        }
        CPA_COMMIT();
    };

    const uint32_t aRow = (uint32_t)((wm * 32 + (lane & 15)) * 144 + (lane >> 4) * 16);
    const int bg = lane >> 3;
    const uint32_t bRow = (uint32_t)((wn * 32 + ((bg >> 1) * 8) + (lane & 7)) * 144
                                     + (bg & 1) * 16);

    load_chunk(0, 0);
    load_chunk(1, 1);

    for (int i = 0; i < kiters; i++) {
        const int s = i & 1;
        if (i + 1 < kiters) asm volatile("cp.async.wait_group 1;" ::: "memory");
        else                asm volatile("cp.async.wait_group 0;" ::: "memory");
        __syncthreads();
        const uint32_t sb = smb + s * FC_STG;
#pragma unroll
        for (int ks = 0; ks < 4; ks++) {
            uint32_t ah[2][4], al[2][4];
#pragma unroll
            for (int mb = 0; mb < 2; mb++) {
                const uint32_t a = sb + aRow + (uint32_t)(mb * 16 * 144 + ks * 32);
                ldm4(a, ah[mb]);
                ldm4(a + FC_ALO, al[mb]);
            }
#pragma unroll
            for (int p = 0; p < 2; p++) {
                uint32_t bh[4];
                ldm4(sb + FC_B + bRow + (uint32_t)(p * 16 * 144 + ks * 32), bh);
#pragma unroll
                for (int mb = 0; mb < 2; mb++)
#pragma unroll
                    for (int half = 0; half < 2; half++) {
                        const int o = half * 2;
                        mma16816h(acc[mb][p * 2 + half], ah[mb], bh[o], bh[o + 1]);
                    }
#pragma unroll
                for (int mb = 0; mb < 2; mb++)
#pragma unroll
                    for (int half = 0; half < 2; half++) {
                        const int o = half * 2;
                        mma16816h(acc[mb][p * 2 + half], al[mb], bh[o], bh[o + 1]);
                    }
            }
        }
        __syncthreads();
        if (i + 2 < kiters) load_chunk(i + 2, s);
    }

    const float invs = rsqrtf(1.0f + 1e-5f);
#pragma unroll
    for (int mb = 0; mb < 2; mb++) {
#pragma unroll
        for (int half = 0; half < 2; half++) {
            const int row = m0 + wm * 32 + mb * 16 + (lane >> 2) + half * 8;
            if (row >= M) continue;
#pragma unroll
            for (int nb = 0; nb < 4; nb++) {
#pragma unroll
                for (int jj = 0; jj < 2; jj++) {
                    const int col = n0 + wn * 32 + nb * 8 + (lane & 3) * 2 + jj;
                    if (col < N) {
                        float v = acc[mb][nb][half * 2 + jj];
                        v = (v + bias[col]) * (g2[col] * invs) + b2[col];
                        C[(size_t)row * ldc + col] = fmaxf(v, 0.f);
                    }
                }
            }
        }
    }
}

// ---------------- glue kernels ----------------
__global__ void k_init(const float* __restrict__ nodef, const float* __restrict__ ef,
                       const float* __restrict__ ief,
                       float* __restrict__ x, bf16* __restrict__ xhi, bf16* __restrict__ xlo,
                       bf16* __restrict__ rhi, bf16* __restrict__ rlo,
                       bf16* __restrict__ thi, bf16* __restrict__ tlo,
                       float* __restrict__ agg, float* __restrict__ deg) {
    int idx = blockIdx.x * blockDim.x + threadIdx.x;
    if (idx >= E2 * KPAD) return;
    int row = idx >> 8, d = idx & 255;
    float rv = 0.f;
    if (d < DDIM)
        rv = (row < NEDGE) ? ef[row * DDIM + d] : ief[(row - NEDGE) * DDIM + d];
    bf16 h, l; split2(rv, h, l);
    rhi[idx] = h; rlo[idx] = l;
    if (d >= DDIM) {
        thi[idx] = __float2bfloat16(0.f);
        tlo[idx] = __float2bfloat16(0.f);
    }
    if (row < MPADX) {
        float xv = (row < NNODES && d < DDIM) ? nodef[row * DDIM + d] : 0.f;
        split2(xv, h, l);
        xhi[idx] = h; xlo[idx] = l;
    }
    if (idx < NNODES * DDIM) { x[idx] = nodef[idx]; agg[idx] = 0.f; }
    if (idx < 2 * NNODES) deg[idx] = 0.f;
}

__global__ void k_deg(const int* __restrict__ ei, const int* __restrict__ iei,
                      float* __restrict__ deg) {
    int e = blockIdx.x * blockDim.x + threadIdx.x;
    if (e < NEDGE) {
        atomicAdd(&deg[ei[e]], 1.f);
        atomicAdd(&deg[NNODES + iei[e]], 1.f);
    }
}

__device__ __forceinline__ float dinvf(float v) { return v > 0.f ? rsqrtf(v) : 0.f; }

__global__ void k_norm(const int* __restrict__ ei, const int* __restrict__ iei,
                       const float* __restrict__ deg, float* __restrict__ sc) {
    int e = blockIdx.x * blockDim.x + threadIdx.x;
    if (e < NEDGE) {
        sc[e]         = dinvf(deg[ei[e]]) * dinvf(deg[ei[NEDGE + e]]);
        sc[NEDGE + e] = dinvf(deg[NNODES + iei[e]]) * dinvf(deg[NNODES + iei[NEDGE + e]]);
    }
}

// t = x[src] - rel, 2 elements per thread
__global__ void k_compose(const int* __restrict__ ei, const int* __restrict__ iei,
                          const float* __restrict__ x,
                          const bf16* __restrict__ rhi, const bf16* __restrict__ rlo,
                          bf16* __restrict__ thi, bf16* __restrict__ tlo) {
    int idx = blockIdx.x * blockDim.x + threadIdx.x;
    if (idx >= E2 * (DDIM / 2)) return;
    int row = idx / (DDIM / 2);
    int dp = (idx - row * (DDIM / 2)) * 2;
    int src = (row < NEDGE) ? ei[row] : iei[row - NEDGE];
    const float2 xv = *(const float2*)&x[src * DDIM + dp];
    const int ridx = row * KPAD + dp;
    const __nv_bfloat162 rh = *(const __nv_bfloat162*)&rhi[ridx];
    const __nv_bfloat162 rl = *(const __nv_bfloat162*)&rlo[ridx];
    float v0 = xv.x - (__bfloat162float(rh.x) + __bfloat162float(rl.x));
    float v1 = xv.y - (__bfloat162float(rh.y) + __bfloat162float(rl.y));
    bf16 h0, l0, h1, l1;
    split2(v0, h0, l0);
    split2(v1, h1, l1);
    *(__nv_bfloat162*)&thi[ridx] = __nv_bfloat162(h0, h1);
    *(__nv_bfloat162*)&tlo[ridx] = __nv_bfloat162(l0, l1);
}

// tanh activation, 2 elems/thread; re-zeroes agg
__global__ void k_act(const float* __restrict__ aggc, float* __restrict__ aggz,
                      const float* __restrict__ b, float* __restrict__ x,
                      bf16* __restrict__ xhi, bf16* __restrict__ xlo) {
    int idx = blockIdx.x * blockDim.x + threadIdx.x;
    if (idx >= NNODES * (DDIM / 2)) return;
    int row = idx / (DDIM / 2);
    int dp = (idx - row * (DDIM / 2)) * 2;
    const int gi = row * DDIM + dp;
    const float2 a = *(const float2*)&aggc[gi];
    *(float2*)&aggz[gi] = make_float2(0.f, 0.f);
    float v0 = tanhf(a.x * (1.0f / 3.0f) + b[dp]);
    float v1 = tanhf(a.y * (1.0f / 3.0f) + b[dp + 1]);
    *(float2*)&x[gi] = make_float2(v0, v1);
    bf16 h0, l0, h1, l1;
    split2(v0, h0, l0);
    split2(v1, h1, l1);
    const int ridx = row * KPAD + dp;
    *(__nv_bfloat162*)&xhi[ridx] = __nv_bfloat162(h0, h1);
    *(__nv_bfloat162*)&xlo[ridx] = __nv_bfloat162(l0, l1);
}

// weight prep: 24 matrices [200,200] -> transposed bf16 hi/lo [256,256]
__global__ void k_prep_wt(const float* __restrict__ Win, const float* __restrict__ Wout,
                          const float* __restrict__ Wloop, const float* __restrict__ Wrel,
                          bf16* __restrict__ hi, bf16* __restrict__ lo) {
    int idx = blockIdx.x * blockDim.x + threadIdx.x;
    if (idx >= 24 * KPAD * KPAD) return;
    int m = idx >> 16;
    int n = (idx >> 8) & 255;
    int k = idx & 255;
    float v = 0.f;
    if (n < DDIM && k < DDIM) {
        int t = m / 6, l = m % 6;
        const float* s = (t == 0) ? Win : (t == 1) ? Wout : (t == 2) ? Wloop : Wrel;
        v = s[l * DDIM * DDIM + k * DDIM + n];
    }
    bf16 h, l2; split2(v, h, l2);
    hi[idx] = h; lo[idx] = l2;
}

// fc_w [200, FLATSZ] -> fp16 [256, FLATSZ] (rows >= 200 zero)
__global__ void k_prep_fc(const float* __restrict__ fcw, f16* __restrict__ w16) {
    size_t idx = (size_t)blockIdx.x * blockDim.x + threadIdx.x;
    if (idx >= (size_t)256 * FLATSZ) return;
    int r = (int)(idx / FLATSZ);
    float v = (r < DDIM) ? fcw[idx] : 0.f;
    w16[idx] = __float2half(v);
}

// ---------------- ConvE conv, FFMA2 filter-pair version; writes fp16 hi/lo ----------------
__global__ void __launch_bounds__(224, 2)
k_conv(const int* __restrict__ ei, const float* __restrict__ x,
       const bf16* __restrict__ rhi, const bf16* __restrict__ rlo,
       const float* __restrict__ conv_w, const float* __restrict__ conv_b,
       const float* __restrict__ bn0g, const float* __restrict__ bn0b,
       const float* __restrict__ bn1g, const float* __restrict__ bn1b,
       f16* __restrict__ hfhi, f16* __restrict__ hflo) {
    __shared__ __align__(16) u64 wp[48][50];
    __shared__ float img[400];
    __shared__ float cb[NFILT], s1[NFILT], b1[NFILT];

    const int e = blockIdx.x;
    const int tid = threadIdx.x;
    const float invs = rsqrtf(1.0f + 1e-5f);

    for (int i = tid; i < 48 * 50; i += 224) {
        int f2 = i / 50, t = i - f2 * 50;
        wp[f2][t] = (t < 49) ? pk2(conv_w[(2 * f2) * 49 + t], conv_w[(2 * f2 + 1) * 49 + t])
                             : 0ULL;
    }
    for (int i = tid; i < NFILT; i += 224) {
        cb[i] = conv_b[i];
        s1[i] = bn1g[i] * invs;
        b1[i] = bn1b[i];
    }
    const float sc0 = bn0g[0] * invs;
    const float bb0 = bn0b[0];
    const int sub = ei[e];
    for (int i = tid; i < 400; i += 224) {
        int ii = i / 20, jj = i - ii * 20;
        int k = ii * 10 + (jj >> 1);
        float v;
        if (jj & 1)
            v = __bfloat162float(rhi[e * KPAD + k]) + __bfloat162float(rlo[e * KPAD + k]);
        else
            v = x[sub * DDIM + k];
        img[i] = v * sc0 + bb0;
    }
    __syncthreads();

    if (tid < 196) {
        const int oi = tid / 14, oj = tid - oi * 14;
        u64 pd[50];
#pragma unroll
        for (int a = 0; a < 7; a++)
#pragma unroll
            for (int b = 0; b < 7; b++) {
                float p = img[(oi + a) * 20 + oj + b];
                pd[a * 7 + b] = pk2(p, p);
            }
        pd[49] = 0ULL;

        const size_t obase = (size_t)e * FLATSZ + tid;
        for (int f2 = 0; f2 < 48; f2++) {
            u64 acc = 0ULL;
#pragma unroll
            for (int t2 = 0; t2 < 25; t2++) {
                ulonglong2 w2 = *(const ulonglong2*)&wp[f2][2 * t2];
                fma2(acc, pd[2 * t2], w2.x);
                fma2(acc, pd[2 * t2 + 1], w2.y);
            }
            float2 vv = unpk(acc);
            const int f0 = 2 * f2, f1 = 2 * f2 + 1;
            float v0 = fmaxf((vv.x + cb[f0]) * s1[f0] + b1[f0], 0.f);
            float v1 = fmaxf((vv.y + cb[f1]) * s1[f1] + b1[f1], 0.f);
            f16 h, l;
            split2h(v0, h, l);
            hfhi[obase + (size_t)f0 * 196] = h; hflo[obase + (size_t)f0 * 196] = l;
            split2h(v1, h, l);
            hfhi[obase + (size_t)f1 * 196] = h; hflo[obase + (size_t)f1 * 196] = l;
        }
    }
}

// ---------------- final tiny FC ----------------
__global__ void k_fc1(const float* __restrict__ h2, const float* __restrict__ fc1w,
                      const float* __restrict__ fc1b, float* __restrict__ out) {
    int idx = blockIdx.x * blockDim.x + threadIdx.x;
    if (idx < NEDGE * NCLASS) {
        int e = idx / NCLASS, c = idx - e * NCLASS;
        const float* h = h2 + e * DDIM;
        const float* w = fc1w + c * DDIM;
        float s = fc1b[c];
#pragma unroll 4
        for (int k = 0; k < DDIM; k++) s += h[k] * w[k];
        out[idx] = s;
    }
}

// ---------------- host launcher ----------------
extern "C" void kernel_launch(void* const* d_in, const int* in_sizes, int n_in,
                              void* d_out, int out_size) {
    const float* nodef = (const float*)d_in[0];
    const float* ef    = (const float*)d_in[1];
    const float* ief   = (const float*)d_in[2];
    const float* Win   = (const float*)d_in[3];
    const float* Wout  = (const float*)d_in[4];
    const float* Wloop = (const float*)d_in[5];
    const float* Wrel  = (const float*)d_in[6];
    const float* bgcn  = (const float*)d_in[7];
    const float* bn0g  = (const float*)d_in[8];
    const float* bn0b  = (const float*)d_in[9];
    const float* convw = (const float*)d_in[10];
    const float* convb = (const float*)d_in[11];
    const float* bn1g  = (const float*)d_in[12];
    const float* bn1b  = (const float*)d_in[13];
    const float* fcw   = (const float*)d_in[14];
    const float* fcb   = (const float*)d_in[15];
    const float* bn2g  = (const float*)d_in[16];
    const float* bn2b  = (const float*)d_in[17];
    const float* fc1w  = (const float*)d_in[18];
    const float* fc1b  = (const float*)d_in[19];
    const int*   ei    = (const int*)d_in[20];
    const int*   iei   = (const int*)d_in[21];
    float* out = (float*)d_out;

    float *px, *pagg, *pdeg, *psc, *ph2;
    bf16 *pxhi, *pxlo, *prhi0, *prlo0, *pthi, *ptlo, *pwthi, *pwtlo;
    f16 *phfhi, *phflo, *pfch;
    cudaGetSymbolAddress((void**)&px,    g_x);
    cudaGetSymbolAddress((void**)&pxhi,  g_xhi);
    cudaGetSymbolAddress((void**)&pxlo,  g_xlo);
    cudaGetSymbolAddress((void**)&prhi0, g_relhi);
    cudaGetSymbolAddress((void**)&prlo0, g_rello);
    cudaGetSymbolAddress((void**)&pthi,  g_thi);
    cudaGetSymbolAddress((void**)&ptlo,  g_tlo);
    cudaGetSymbolAddress((void**)&pagg,  g_agg);
    cudaGetSymbolAddress((void**)&pdeg,  g_deg);
    cudaGetSymbolAddress((void**)&psc,   g_scale);
    cudaGetSymbolAddress((void**)&phfhi, g_hfhi);
    cudaGetSymbolAddress((void**)&phflo, g_hflo);
    cudaGetSymbolAddress((void**)&ph2,   g_h2);
    cudaGetSymbolAddress((void**)&pwthi, g_wthi);
    cudaGetSymbolAddress((void**)&pwtlo, g_wtlo);
    cudaGetSymbolAddress((void**)&pfch,  g_fch);

    const int GEMM_SMEM = 2 * STGBYTES;
    const int FC_SMEM   = 2 * FC_STG;
    cudaFuncSetAttribute(gemm_multi, cudaFuncAttributeMaxDynamicSharedMemorySize, GEMM_SMEM);
    cudaFuncSetAttribute(gemm_fc,    cudaFuncAttributeMaxDynamicSharedMemorySize, FC_SMEM);

    const int RELSZ = E2 * KPAD;
    const int WMAT = KPAD * KPAD;
    const int NONE_SW = 0x40000000;

    auto make_jobs = [&](int l, int cur, GemmJob& j0, GemmJob& j1, GemmJob& j2) {
        bf16* rhi_c = prhi0 + cur * RELSZ;
        bf16* rlo_c = prlo0 + cur * RELSZ;
        bf16* rhi_n = prhi0 + (1 - cur) * RELSZ;
        bf16* rlo_n = prlo0 + (1 - cur) * RELSZ;
        j0 = { pthi, ptlo, KPAD,
               pwthi + (0 * 6 + l) * WMAT, pwtlo + (0 * 6 + l) * WMAT,
               pwthi + (1 * 6 + l) * WMAT, pwtlo + (1 * 6 + l) * WMAT, NEDGE,
               KPAD, KPAD / 64, E2 / 128,
               pagg, DDIM, E2, DDIM, nullptr, nullptr, 0, ei, iei, psc, 3 };
        j1 = { pxhi, pxlo, KPAD,
               pwthi + (2 * 6 + l) * WMAT, pwtlo + (2 * 6 + l) * WMAT,
               pwthi + (2 * 6 + l) * WMAT, pwtlo + (2 * 6 + l) * WMAT, NONE_SW,
               KPAD, KPAD / 64, MPADX / 128,
               pagg, DDIM, NNODES, DDIM, nullptr, nullptr, 0,
               nullptr, nullptr, nullptr, 4 };
        j2 = { rhi_c, rlo_c, KPAD,
               pwthi + (3 * 6 + l) * WMAT, pwtlo + (3 * 6 + l) * WMAT,
               pwthi + (3 * 6 + l) * WMAT, pwtlo + (3 * 6 + l) * WMAT, NONE_SW,
               KPAD, KPAD / 64, E2 / 128,
               nullptr, 0, E2, DDIM, rhi_n, rlo_n, KPAD,
               nullptr, nullptr, nullptr, 2 };
    };

    k_init<<<(E2 * KPAD + 255) / 256, 256>>>(nodef, ef, ief, px, pxhi, pxlo,
                                             prhi0, prlo0, pthi, ptlo, pagg, pdeg);
    k_prep_wt<<<(24 * WMAT + 255) / 256, 256>>>(Win, Wout, Wloop, Wrel, pwthi, pwtlo);
    k_deg<<<(NEDGE + 255) / 256, 256>>>(ei, iei, pdeg);
    k_compose<<<(E2 * (DDIM / 2) + 255) / 256, 256>>>(ei, iei, px, prhi0, prlo0,
                                                      pthi, ptlo);
    k_norm<<<(NEDGE + 255) / 256, 256>>>(ei, iei, pdeg, psc);
    k_prep_fc<<<(int)(((size_t)256 * FLATSZ + 255) / 256), 256>>>(fcw, pfch);

    dim3 gMulti(4, 128, 3);
    int cur = 0;
    for (int l = 0; l < NLAYER; l++) {
        if (l > 0) {
            bf16* rhi_c = prhi0 + cur * RELSZ;
            bf16* rlo_c = prlo0 + cur * RELSZ;
            k_compose<<<(E2 * (DDIM / 2) + 255) / 256, 256>>>(ei, iei, px, rhi_c, rlo_c,
                                                              pthi, ptlo);
        }
        GemmJob j0, j1, j2;
        make_jobs(l, cur, j0, j1, j2);
        gemm_multi<<<gMulti, 256, GEMM_SMEM>>>(j0, j1, j2);
        k_act<<<(NNODES * (DDIM / 2) + 255) / 256, 256>>>(pagg, pagg, bgcn + l * DDIM,
                                                          px, pxhi, pxlo);
        cur ^= 1;
    }
    bf16* rhi_f = prhi0 + cur * RELSZ;
    bf16* rlo_f = prlo0 + cur * RELSZ;

    k_conv<<<NEDGE, 224>>>(ei, px, rhi_f, rlo_f, convw, convb,
                           bn0g, bn0b, bn1g, bn1b, phfhi, phflo);

    dim3 gFC(4, NEDGE / 128);
    gemm_fc<<<gFC, 256, FC_SMEM>>>(phfhi, phflo, FLATSZ, pfch, FLATSZ, FLATSZ / 64,
                                   ph2, DDIM, NEDGE, DDIM, fcb, bn2g, bn2b);

    k_fc1<<<(NEDGE * NCLASS + 255) / 256, 256>>>(ph2, fc1w, fc1b, out);
}